// round 7
// baseline (speedup 1.0000x reference)
#include <cuda_runtime.h>
#include <cuda_bf16.h>
#include <math.h>
#include <stdint.h>

typedef unsigned long long u64;
typedef unsigned int u32;

// ---------------- problem constants ----------------
#define BSZ   4096
#define DIM   128
#define KNBR  64
#define NREL  16
#define KAGG  2048          // NREL * DIM
#define KCAT  2176          // KAGG + DIM
#define NQKV  384
#define NSPLIT 4
#define KCHUNK 544          // KCAT / NSPLIT -> 17 k-tiles of 32

// ---------------- device scratch ----------------
__device__ __nv_bfloat16 g_aggh[BSZ * KAGG];
__device__ __nv_bfloat16 g_aggl[BSZ * KAGG];
__device__ float         g_x   [3][BSZ * DIM];        // fp32 x0,x1 (residuals)
__device__ __nv_bfloat16 g_xh  [3 * BSZ * DIM];       // x0,x1,x2 hi
__device__ __nv_bfloat16 g_xl  [3 * BSZ * DIM];       // x0,x1,x2 lo
__device__ float         g_qkv [2 * BSZ * NQKV];
__device__ __nv_bfloat16 g_oh  [BSZ * DIM];
__device__ __nv_bfloat16 g_ol  [BSZ * DIM];
__device__ __nv_bfloat16 g_Wth [2 * DIM * KCAT];      // B for layer gemm, [l][e][k]
__device__ __nv_bfloat16 g_Wtl [2 * DIM * KCAT];
__device__ __nv_bfloat16 g_inh [NQKV * DIM];
__device__ __nv_bfloat16 g_inl [NQKV * DIM];
__device__ __nv_bfloat16 g_outh[DIM * DIM];
__device__ __nv_bfloat16 g_outl[DIM * DIM];
__device__ float         g_part[NSPLIT * BSZ * DIM];

// ================= PTX helpers =================
__device__ __forceinline__ u32 smem_u32(const void* p) {
    u32 a; asm("{ .reg .u64 t; cvta.to.shared.u64 t, %1; cvt.u32.u64 %0, t; }" : "=r"(a) : "l"(p));
    return a;
}
__device__ __forceinline__ void cp16(u32 s, const void* g) {
    asm volatile("cp.async.cg.shared.global [%0], [%1], 16;" :: "r"(s), "l"(g));
}
__device__ __forceinline__ void cp_commit() {
    asm volatile("cp.async.commit_group;" ::: "memory");
}
__device__ __forceinline__ void cp_wait0() {
    asm volatile("cp.async.wait_group 0;" ::: "memory");
}
__device__ __forceinline__ void cp_wait1() {
    asm volatile("cp.async.wait_group 1;" ::: "memory");
}
__device__ __forceinline__ void ldsm4(u32* r, u32 addr) {
    asm volatile("ldmatrix.sync.aligned.m8n8.x4.shared.b16 {%0,%1,%2,%3}, [%4];"
                 : "=r"(r[0]), "=r"(r[1]), "=r"(r[2]), "=r"(r[3]) : "r"(addr));
}
__device__ __forceinline__ void mma16816(float* c, const u32* a, const u32* b) {
    asm volatile(
        "mma.sync.aligned.m16n8k16.row.col.f32.bf16.bf16.f32 "
        "{%0,%1,%2,%3}, {%4,%5,%6,%7}, {%8,%9}, {%0,%1,%2,%3};"
        : "+f"(c[0]), "+f"(c[1]), "+f"(c[2]), "+f"(c[3])
        : "r"(a[0]), "r"(a[1]), "r"(a[2]), "r"(a[3]), "r"(b[0]), "r"(b[1]));
}
__device__ __forceinline__ void split_bf16(float v, __nv_bfloat16& h, __nv_bfloat16& l) {
    h = __float2bfloat16_rn(v);
    l = __float2bfloat16_rn(v - __bfloat162float(h));
}

// ================= prep kernels =================
// W_rel[l,r,d,e] -> B[l][e][r*128+d]  (bf16 hi/lo)
__global__ void transpose_wrel(const float* __restrict__ Wrel)
{
    __shared__ float tile[32][33];
    const int mat = blockIdx.z;           // l*16 + r
    const int l = mat >> 4, r = mat & 15;
    const int tx = threadIdx.x, ty = threadIdx.y;
    const float* src = Wrel + (long)mat * 16384;
    int e_in = blockIdx.x * 32 + tx;
    #pragma unroll
    for (int i = 0; i < 4; i++) {
        int d = blockIdx.y * 32 + ty + i * 8;
        tile[ty + i * 8][tx] = src[d * 128 + e_in];
    }
    __syncthreads();
    const long base = (long)l * (DIM * KCAT);
    #pragma unroll
    for (int i = 0; i < 4; i++) {
        int e = blockIdx.x * 32 + ty + i * 8;
        int d = blockIdx.y * 32 + tx;
        float v = tile[tx][ty + i * 8];
        __nv_bfloat16 h, lo; split_bf16(v, h, lo);
        long o = base + (long)e * KCAT + r * 128 + d;
        g_Wth[o] = h; g_Wtl[o] = lo;
    }
}

// res_W[l,e,d] -> B[l][e][2048+d]; plus inW / outW straight conversion
__global__ void prep_rest(const float* __restrict__ resW,
                          const float* __restrict__ inW,
                          const float* __restrict__ outW)
{
    int i = blockIdx.x * 256 + threadIdx.x;
    const int NR = 2 * DIM * DIM;         // 32768
    const int NI = NQKV * DIM;            // 49152
    const int NO = DIM * DIM;             // 16384
    if (i < NR) {
        int l = i >> 14, e = (i >> 7) & 127, d = i & 127;
        __nv_bfloat16 h, lo; split_bf16(resW[i], h, lo);
        long o = (long)l * (DIM * KCAT) + (long)e * KCAT + 2048 + d;
        g_Wth[o] = h; g_Wtl[o] = lo;
    } else if (i < NR + NI) {
        int t = i - NR;
        __nv_bfloat16 h, lo; split_bf16(inW[t], h, lo);
        g_inh[t] = h; g_inl[t] = lo;
    } else if (i < NR + NI + NO) {
        int t = i - NR - NI;
        __nv_bfloat16 h, lo; split_bf16(outW[t], h, lo);
        g_outh[t] = h; g_outl[t] = lo;
    }
}

// ---------------- agg: relation scatter + x0 gather (bf16 hi/lo outputs) ----
__global__ void __launch_bounds__(128)
agg_kernel(const int* __restrict__ drug,
           const int* __restrict__ adjE,
           const int* __restrict__ adjR,
           const float* __restrict__ ew,
           const float* __restrict__ E)
{
    __shared__ float s[NREL * DIM];
    __shared__ int   se[KNBR];
    __shared__ int   sr[KNBR];
    __shared__ float sw[KNBR];

    const int b = blockIdx.x;
    const int d = threadIdx.x;

    #pragma unroll
    for (int r = 0; r < NREL; r++) s[r * DIM + d] = 0.f;

    if (d < KNBR) {
        se[d] = adjE[b * KNBR + d];
        sr[d] = adjR[b * KNBR + d];
        sw[d] = ew  [b * KNBR + d];
    }
    {
        float v = E[(long)drug[b] * DIM + d];
        g_x[0][b * DIM + d] = v;
        __nv_bfloat16 h, lo; split_bf16(v, h, lo);
        g_xh[b * DIM + d] = h; g_xl[b * DIM + d] = lo;
    }
    __syncthreads();

    #pragma unroll 1
    for (int k = 0; k < KNBR; k += 4) {
        float e0 = E[(long)se[k + 0] * DIM + d];
        float e1 = E[(long)se[k + 1] * DIM + d];
        float e2 = E[(long)se[k + 2] * DIM + d];
        float e3 = E[(long)se[k + 3] * DIM + d];
        s[sr[k + 0] * DIM + d] += sw[k + 0] * e0;
        s[sr[k + 1] * DIM + d] += sw[k + 1] * e1;
        s[sr[k + 2] * DIM + d] += sw[k + 2] * e2;
        s[sr[k + 3] * DIM + d] += sw[k + 3] * e3;
    }
    const long ao = (long)b * KAGG;
    #pragma unroll
    for (int r = 0; r < NREL; r++) {
        float v = s[r * DIM + d];
        __nv_bfloat16 h, lo; split_bf16(v, h, lo);
        g_aggh[ao + r * DIM + d] = h;
        g_aggl[ao + r * DIM + d] = lo;
    }
}

// ================= bf16 hi/lo 3-pass tensor-core GEMM =================
// 512 threads / 16 warps; CTA tile 128x128; warp tile 32x32.
// C[m,n] = sum_k A[m,k]*B[n,k]; A = [A1 | A2] (K1 + K2 cols), bf16 hi/lo pairs.
// SMEM: 3 stages x { Ah, Al, Bh, Bl } each 128 rows x 80B (32 bf16 + pad)
#define ROWB   80
#define REGB   10240            // 128 * 80
#define STAGEB 40960
#define GT_SMEM (3 * STAGEB)

__global__ void __launch_bounds__(512, 1)
gemm_bf16(const __nv_bfloat16* __restrict__ A1h, const __nv_bfloat16* __restrict__ A1l, int K1,
          const __nv_bfloat16* __restrict__ A2h, const __nv_bfloat16* __restrict__ A2l, int K2,
          const __nv_bfloat16* __restrict__ Bh,  const __nv_bfloat16* __restrict__ Bl,  int KB,
          float* __restrict__ C, int ldC, long partStride,
          int kchunk, int ntiles, const float* __restrict__ bias)
{
    extern __shared__ __align__(128) char smem[];
    const u32 sb  = smem_u32(smem);
    const int tid = threadIdx.x, lane = tid & 31, wid = tid >> 5;
    const int bm  = blockIdx.x * 128;
    const int bn  = blockIdx.y * 128;
    const int kbeg = blockIdx.z * kchunk;

    // producer: thread -> (buffer 0..3 = Ah,Al,Bh,Bl ; row 0..127), 4x cp16 per tile
    const int pbuf = tid >> 7;
    const int prow = tid & 127;

    auto issue = [&](int t, int s) {
        const int k0 = kbeg + t * 32;
        const __nv_bfloat16* src;
        if (pbuf < 2) {
            if (k0 < K1) {
                long o = (long)(bm + prow) * K1 + k0;
                src = (pbuf == 0 ? A1h : A1l) + o;
            } else {
                long o = (long)(bm + prow) * K2 + (k0 - K1);
                src = (pbuf == 0 ? A2h : A2l) + o;
            }
        } else {
            long o = (long)(bn + prow) * KB + k0;
            src = (pbuf == 2 ? Bh : Bl) + o;
        }
        u32 d = sb + s * STAGEB + pbuf * REGB + prow * ROWB;
        cp16(d,      src);      cp16(d + 16, src + 8);
        cp16(d + 32, src + 16); cp16(d + 48, src + 24);
        cp_commit();
    };

    // consumer: 16 warps -> 4 (m) x 4 (n); warp tile 32x32
    const int wr = wid & 3, wc = wid >> 2;
    const u32 a_off = (u32)((wr * 32 + (lane & 15)) * ROWB + (lane >> 4) * 16);
    const u32 b_off = (u32)(2 * REGB +
                            (wc * 32 + (lane & 7) + ((lane >> 4) & 1) * 8) * ROWB +
                            ((lane >> 3) & 1) * 16);

    float acc[2][4][4];
    #pragma unroll
    for (int i = 0; i < 2; i++)
        #pragma unroll
        for (int j = 0; j < 4; j++)
            #pragma unroll
            for (int q = 0; q < 4; q++) acc[i][j][q] = 0.f;

    issue(0, 0);
    if (ntiles > 1) issue(1, 1);

    for (int t = 0; t < ntiles; t++) {
        const int s = t % 3;
        if (t + 1 < ntiles) cp_wait1(); else cp_wait0();
        __syncthreads();   // smem(t) visible; all warps done with stage (t+2)%3
        if (t + 2 < ntiles) issue(t + 2, (t + 2) % 3);

        const u32 base = sb + s * STAGEB;
        #pragma unroll
        for (int kk = 0; kk < 32; kk += 16) {
            u32 ah[2][4], al[2][4], bh[2][4], bl[2][4];
            #pragma unroll
            for (int mi = 0; mi < 2; mi++) {
                ldsm4(ah[mi], base + a_off + mi * (16 * ROWB) + kk * 2);
                ldsm4(al[mi], base + REGB + a_off + mi * (16 * ROWB) + kk * 2);
            }
            #pragma unroll
            for (int nj = 0; nj < 2; nj++) {
                ldsm4(bh[nj], base + b_off + nj * (16 * ROWB) + kk * 2);
                ldsm4(bl[nj], base + REGB + b_off + nj * (16 * ROWB) + kk * 2);
            }
            // pass-major ordering: 8 independent MMAs per pass
            #pragma unroll
            for (int mi = 0; mi < 2; mi++)
                #pragma unroll
                for (int nt = 0; nt < 4; nt++)
                    mma16816(acc[mi][nt], ah[mi], &bh[nt >> 1][(nt & 1) * 2]);
            #pragma unroll
            for (int mi = 0; mi < 2; mi++)
                #pragma unroll
                for (int nt = 0; nt < 4; nt++)
                    mma16816(acc[mi][nt], ah[mi], &bl[nt >> 1][(nt & 1) * 2]);
            #pragma unroll
            for (int mi = 0; mi < 2; mi++)
                #pragma unroll
                for (int nt = 0; nt < 4; nt++)
                    mma16816(acc[mi][nt], al[mi], &bh[nt >> 1][(nt & 1) * 2]);
        }
    }

    // epilogue
    float* Cp = C + (long)blockIdx.z * partStride;
    const int gr  = bm + wr * 32 + (lane >> 2);
    const int gcb = bn + wc * 32 + (lane & 3) * 2;
    #pragma unroll
    for (int mi = 0; mi < 2; mi++)
        #pragma unroll
        for (int nt = 0; nt < 4; nt++) {
            int r0 = gr + mi * 16;
            int c  = gcb + nt * 8;
            float b0 = 0.f, b1 = 0.f;
            if (bias) { b0 = bias[c]; b1 = bias[c + 1]; }
            float2 v0 = make_float2(acc[mi][nt][0] + b0, acc[mi][nt][1] + b1);
            float2 v1 = make_float2(acc[mi][nt][2] + b0, acc[mi][nt][3] + b1);
            *(float2*)(Cp + (long)r0 * ldC + c)       = v0;
            *(float2*)(Cp + (long)(r0 + 8) * ldC + c) = v1;
        }
}

// ---------------- split-K combine + bias + residual + relu ----------------
__global__ void __launch_bounds__(256)
combine_layer(const float* __restrict__ bias,
              const float* __restrict__ xin,
              float* __restrict__ xout,
              __nv_bfloat16* __restrict__ xh,
              __nv_bfloat16* __restrict__ xl)
{
    const int i = blockIdx.x * 256 + threadIdx.x;      // over BSZ*DIM/4
    const float4* p = (const float4*)g_part;
    const int Q = BSZ * DIM / 4;
    float4 v0 = p[i], v1 = p[i + Q], v2 = p[i + 2 * Q], v3 = p[i + 3 * Q];
    float4 xi = ((const float4*)xin)[i];
    float4 bb = ((const float4*)bias)[i & 31];
    float4 o;
    o.x = fmaxf(v0.x + v1.x + v2.x + v3.x + xi.x + bb.x, 0.f);
    o.y = fmaxf(v0.y + v1.y + v2.y + v3.y + xi.y + bb.y, 0.f);
    o.z = fmaxf(v0.z + v1.z + v2.z + v3.z + xi.z + bb.z, 0.f);
    o.w = fmaxf(v0.w + v1.w + v2.w + v3.w + xi.w + bb.w, 0.f);
    ((float4*)xout)[i] = o;

    __nv_bfloat16 hx, lx, hy, ly, hz, lz, hw, lw;
    split_bf16(o.x, hx, lx); split_bf16(o.y, hy, ly);
    split_bf16(o.z, hz, lz); split_bf16(o.w, hw, lw);
    __nv_bfloat162* ph = (__nv_bfloat162*)xh;
    __nv_bfloat162* pl = (__nv_bfloat162*)xl;
    ph[2 * i]     = __nv_bfloat162(hx, hy);
    ph[2 * i + 1] = __nv_bfloat162(hz, hw);
    pl[2 * i]     = __nv_bfloat162(lx, ly);
    pl[2 * i + 1] = __nv_bfloat162(lz, lw);
}

// ---------------- attention (L=2, one warp per head) ----------------
__global__ void __launch_bounds__(128)
attn_kernel()
{
    const int b = blockIdx.x;
    const int h = threadIdx.x >> 5;
    const int d = threadIdx.x & 31;

    const float* p0 = g_qkv + (long)b * NQKV + h * 32 + d;
    const float* p1 = p0 + (long)BSZ * NQKV;
    float q0 = p0[0], k0 = p0[128], v0 = p0[256];
    float q1 = p1[0], k1 = p1[128], v1 = p1[256];

    float s00 = q0 * k0, s01 = q0 * k1, s10 = q1 * k0, s11 = q1 * k1;
    #pragma unroll
    for (int o = 16; o; o >>= 1) {
        s00 += __shfl_xor_sync(0xffffffffu, s00, o);
        s01 += __shfl_xor_sync(0xffffffffu, s01, o);
        s10 += __shfl_xor_sync(0xffffffffu, s10, o);
        s11 += __shfl_xor_sync(0xffffffffu, s11, o);
    }
    const float inv = 0.17677669529663687f;  // 1/sqrt(32)
    s00 *= inv; s01 *= inv; s10 *= inv; s11 *= inv;

    float m0 = fmaxf(s00, s01), m1 = fmaxf(s10, s11);
    float e00 = expf(s00 - m0), e01 = expf(s01 - m0);
    float e10 = expf(s10 - m1), e11 = expf(s11 - m1);
    float o0 = (e00 * v0 + e01 * v1) / (e00 + e01);
    float o1 = (e10 * v0 + e11 * v1) / (e10 + e11);

    float v = 0.5f * (o0 + o1);
    __nv_bfloat16 hh, ll; split_bf16(v, hh, ll);
    g_oh[(long)b * DIM + h * 32 + d] = hh;
    g_ol[(long)b * DIM + h * 32 + d] = ll;
}

// ---------------- host launcher ----------------
extern "C" void kernel_launch(void* const* d_in, const int* in_sizes, int n_in,
                              void* d_out, int out_size)
{
    const int*   drug = (const int*)  d_in[0];
    const int*   adjE = (const int*)  d_in[1];
    const int*   adjR = (const int*)  d_in[2];
    const float* ew   = (const float*)d_in[3];
    const float* E    = (const float*)d_in[4];
    const float* Wrel = (const float*)d_in[5];
    const float* resW = (const float*)d_in[6];
    const float* resb = (const float*)d_in[7];
    const float* inW  = (const float*)d_in[8];
    const float* inB  = (const float*)d_in[9];
    const float* outW = (const float*)d_in[10];
    const float* outB = (const float*)d_in[11];

    __nv_bfloat16 *aggh, *aggl, *xh, *xl, *oh, *ol, *Wth, *Wtl, *inh, *inl, *outh, *outl;
    float *xf, *qkv, *part;
    cudaGetSymbolAddress((void**)&aggh, g_aggh);
    cudaGetSymbolAddress((void**)&aggl, g_aggl);
    cudaGetSymbolAddress((void**)&xf,   g_x);
    cudaGetSymbolAddress((void**)&xh,   g_xh);
    cudaGetSymbolAddress((void**)&xl,   g_xl);
    cudaGetSymbolAddress((void**)&qkv,  g_qkv);
    cudaGetSymbolAddress((void**)&oh,   g_oh);
    cudaGetSymbolAddress((void**)&ol,   g_ol);
    cudaGetSymbolAddress((void**)&Wth,  g_Wth);
    cudaGetSymbolAddress((void**)&Wtl,  g_Wtl);
    cudaGetSymbolAddress((void**)&inh,  g_inh);
    cudaGetSymbolAddress((void**)&inl,  g_inl);
    cudaGetSymbolAddress((void**)&outh, g_outh);
    cudaGetSymbolAddress((void**)&outl, g_outl);
    cudaGetSymbolAddress((void**)&part, g_part);

    cudaFuncSetAttribute(gemm_bf16, cudaFuncAttributeMaxDynamicSharedMemorySize, GT_SMEM);

    transpose_wrel<<<dim3(4, 4, 32), dim3(32, 8)>>>(Wrel);
    prep_rest<<<(2 * DIM * DIM + NQKV * DIM + DIM * DIM + 255) / 256, 256>>>(resW, inW, outW);
    agg_kernel<<<BSZ, 128>>>(drug, adjE, adjR, ew, E);

    // layer 0: part = split-K((agg|x0) @ Wcat0^T); x1 = relu(sum + b0 + x0)
    gemm_bf16<<<dim3(BSZ / 128, 1, NSPLIT), 512, GT_SMEM>>>(
        aggh, aggl, KAGG, xh, xl, DIM, Wth, Wtl, KCAT,
        part, DIM, (long)BSZ * DIM, KCHUNK, KCHUNK / 32, nullptr);
    combine_layer<<<BSZ * DIM / 4 / 256, 256>>>(
        resb, xf, xf + BSZ * DIM, xh + BSZ * DIM, xl + BSZ * DIM);

    // layer 1
    gemm_bf16<<<dim3(BSZ / 128, 1, NSPLIT), 512, GT_SMEM>>>(
        aggh, aggl, KAGG, xh + BSZ * DIM, xl + BSZ * DIM, DIM,
        Wth + DIM * KCAT, Wtl + DIM * KCAT, KCAT,
        part, DIM, (long)BSZ * DIM, KCHUNK, KCHUNK / 32, nullptr);
    combine_layer<<<BSZ * DIM / 4 / 256, 256>>>(
        resb + DIM, xf + BSZ * DIM, xf + 2 * BSZ * DIM,
        xh + 2 * BSZ * DIM, xl + 2 * BSZ * DIM);

    // qkv for both layer outputs: M=8192 (x1,x2 contiguous), N=384, K=128
    gemm_bf16<<<dim3(2 * BSZ / 128, NQKV / 128, 1), 512, GT_SMEM>>>(
        xh + BSZ * DIM, xl + BSZ * DIM, DIM, nullptr, nullptr, 0,
        inh, inl, DIM, qkv, NQKV, 0, DIM, DIM / 32, inB);

    attn_kernel<<<BSZ, 128>>>();

    // out projection: M=4096, N=128, K=128 -> d_out
    gemm_bf16<<<dim3(BSZ / 128, 1, 1), 512, GT_SMEM>>>(
        oh, ol, DIM, nullptr, nullptr, 0,
        outh, outl, DIM, (float*)d_out, DIM, 0, DIM, DIM / 32, outB);
}

// round 9
// speedup vs baseline: 1.1122x; 1.1122x over previous
#include <cuda_runtime.h>
#include <cuda_bf16.h>
#include <math.h>
#include <stdint.h>

typedef unsigned long long u64;
typedef unsigned int u32;

// ---------------- problem constants ----------------
#define BSZ   4096
#define DIM   128
#define KNBR  64
#define NREL  16
#define KAGG  2048          // NREL * DIM
#define KCAT  2176          // KAGG + DIM
#define NQKV  384
#define NSPLIT 8            // split-K for layer GEMMs (68 tiles -> 8..9 each)
#define LAYER_TILES 68      // KCAT / 32

// ---------------- device scratch ----------------
__device__ __nv_bfloat16 g_aggh[BSZ * KAGG];
__device__ __nv_bfloat16 g_aggl[BSZ * KAGG];
__device__ float         g_x   [3][BSZ * DIM];        // fp32 x0,x1 (residuals)
__device__ __nv_bfloat16 g_xh  [3 * BSZ * DIM];       // x0,x1,x2 hi
__device__ __nv_bfloat16 g_xl  [3 * BSZ * DIM];       // x0,x1,x2 lo
__device__ float         g_qkv [2 * BSZ * NQKV];
__device__ __nv_bfloat16 g_oh  [BSZ * DIM];
__device__ __nv_bfloat16 g_ol  [BSZ * DIM];
__device__ __nv_bfloat16 g_Wth [2 * DIM * KCAT];      // B for layer gemm, [l][e][k]
__device__ __nv_bfloat16 g_Wtl [2 * DIM * KCAT];
__device__ __nv_bfloat16 g_inh [NQKV * DIM];
__device__ __nv_bfloat16 g_inl [NQKV * DIM];
__device__ __nv_bfloat16 g_outh[DIM * DIM];
__device__ __nv_bfloat16 g_outl[DIM * DIM];
__device__ float         g_part[NSPLIT * BSZ * DIM];

// ================= PTX helpers =================
__device__ __forceinline__ u32 smem_u32(const void* p) {
    u32 a; asm("{ .reg .u64 t; cvta.to.shared.u64 t, %1; cvt.u32.u64 %0, t; }" : "=r"(a) : "l"(p));
    return a;
}
__device__ __forceinline__ void cp16(u32 s, const void* g) {
    asm volatile("cp.async.cg.shared.global [%0], [%1], 16;" :: "r"(s), "l"(g));
}
__device__ __forceinline__ void cp_commit() {
    asm volatile("cp.async.commit_group;" ::: "memory");
}
__device__ __forceinline__ void cp_wait0() {
    asm volatile("cp.async.wait_group 0;" ::: "memory");
}
__device__ __forceinline__ void cp_wait1() {
    asm volatile("cp.async.wait_group 1;" ::: "memory");
}
__device__ __forceinline__ void ldsm4(u32* r, u32 addr) {
    asm volatile("ldmatrix.sync.aligned.m8n8.x4.shared.b16 {%0,%1,%2,%3}, [%4];"
                 : "=r"(r[0]), "=r"(r[1]), "=r"(r[2]), "=r"(r[3]) : "r"(addr));
}
__device__ __forceinline__ void mma16816(float* c, const u32* a, const u32* b) {
    asm volatile(
        "mma.sync.aligned.m16n8k16.row.col.f32.bf16.bf16.f32 "
        "{%0,%1,%2,%3}, {%4,%5,%6,%7}, {%8,%9}, {%0,%1,%2,%3};"
        : "+f"(c[0]), "+f"(c[1]), "+f"(c[2]), "+f"(c[3])
        : "r"(a[0]), "r"(a[1]), "r"(a[2]), "r"(a[3]), "r"(b[0]), "r"(b[1]));
}
__device__ __forceinline__ void split_bf16(float v, __nv_bfloat16& h, __nv_bfloat16& l) {
    h = __float2bfloat16_rn(v);
    l = __float2bfloat16_rn(v - __bfloat162float(h));
}

// ================= prep kernels =================
// W_rel[l,r,d,e] -> B[l][e][r*128+d]  (bf16 hi/lo)
__global__ void transpose_wrel(const float* __restrict__ Wrel)
{
    __shared__ float tile[32][33];
    const int mat = blockIdx.z;           // l*16 + r
    const int l = mat >> 4, r = mat & 15;
    const int tx = threadIdx.x, ty = threadIdx.y;
    const float* src = Wrel + (long)mat * 16384;
    int e_in = blockIdx.x * 32 + tx;
    #pragma unroll
    for (int i = 0; i < 4; i++) {
        int d = blockIdx.y * 32 + ty + i * 8;
        tile[ty + i * 8][tx] = src[d * 128 + e_in];
    }
    __syncthreads();
    const long base = (long)l * (DIM * KCAT);
    #pragma unroll
    for (int i = 0; i < 4; i++) {
        int e = blockIdx.x * 32 + ty + i * 8;
        int d = blockIdx.y * 32 + tx;
        float v = tile[tx][ty + i * 8];
        __nv_bfloat16 h, lo; split_bf16(v, h, lo);
        long o = base + (long)e * KCAT + r * 128 + d;
        g_Wth[o] = h; g_Wtl[o] = lo;
    }
}

// res_W[l,e,d] -> B[l][e][2048+d]; plus inW / outW straight conversion
__global__ void prep_rest(const float* __restrict__ resW,
                          const float* __restrict__ inW,
                          const float* __restrict__ outW)
{
    int i = blockIdx.x * 256 + threadIdx.x;
    const int NR = 2 * DIM * DIM;         // 32768
    const int NI = NQKV * DIM;            // 49152
    const int NO = DIM * DIM;             // 16384
    if (i < NR) {
        int l = i >> 14, e = (i >> 7) & 127, d = i & 127;
        __nv_bfloat16 h, lo; split_bf16(resW[i], h, lo);
        long o = (long)l * (DIM * KCAT) + (long)e * KCAT + 2048 + d;
        g_Wth[o] = h; g_Wtl[o] = lo;
    } else if (i < NR + NI) {
        int t = i - NR;
        __nv_bfloat16 h, lo; split_bf16(inW[t], h, lo);
        g_inh[t] = h; g_inl[t] = lo;
    } else if (i < NR + NI + NO) {
        int t = i - NR - NI;
        __nv_bfloat16 h, lo; split_bf16(outW[t], h, lo);
        g_outh[t] = h; g_outl[t] = lo;
    }
}

// ---------------- agg: relation scatter + x0 gather (bf16 hi/lo outputs) ----
__global__ void __launch_bounds__(128)
agg_kernel(const int* __restrict__ drug,
           const int* __restrict__ adjE,
           const int* __restrict__ adjR,
           const float* __restrict__ ew,
           const float* __restrict__ E)
{
    __shared__ float s[NREL * DIM];
    __shared__ int   se[KNBR];
    __shared__ int   sr[KNBR];
    __shared__ float sw[KNBR];

    const int b = blockIdx.x;
    const int d = threadIdx.x;

    #pragma unroll
    for (int r = 0; r < NREL; r++) s[r * DIM + d] = 0.f;

    if (d < KNBR) {
        se[d] = adjE[b * KNBR + d];
        sr[d] = adjR[b * KNBR + d];
        sw[d] = ew  [b * KNBR + d];
    }
    {
        float v = E[(long)drug[b] * DIM + d];
        g_x[0][b * DIM + d] = v;
        __nv_bfloat16 h, lo; split_bf16(v, h, lo);
        g_xh[b * DIM + d] = h; g_xl[b * DIM + d] = lo;
    }
    __syncthreads();

    #pragma unroll 1
    for (int k = 0; k < KNBR; k += 4) {
        float e0 = E[(long)se[k + 0] * DIM + d];
        float e1 = E[(long)se[k + 1] * DIM + d];
        float e2 = E[(long)se[k + 2] * DIM + d];
        float e3 = E[(long)se[k + 3] * DIM + d];
        s[sr[k + 0] * DIM + d] += sw[k + 0] * e0;
        s[sr[k + 1] * DIM + d] += sw[k + 1] * e1;
        s[sr[k + 2] * DIM + d] += sw[k + 2] * e2;
        s[sr[k + 3] * DIM + d] += sw[k + 3] * e3;
    }
    const long ao = (long)b * KAGG;
    #pragma unroll
    for (int r = 0; r < NREL; r++) {
        float v = s[r * DIM + d];
        __nv_bfloat16 h, lo; split_bf16(v, h, lo);
        g_aggh[ao + r * DIM + d] = h;
        g_aggl[ao + r * DIM + d] = lo;
    }
}

// ================= bf16 hi/lo 3-pass tensor-core GEMM =================
// 256 threads / 8 warps; CTA tile 128x128; warp tile 32x64; 2 CTAs/SM.
// C[m,n] = sum_k A[m,k]*B[n,k]; A = [A1 | A2] (K1 + K2 cols), bf16 hi/lo pairs.
// k-range per blockIdx.z: tiles [tiles_total*z/Z, tiles_total*(z+1)/Z).
// SMEM: 2 stages x { Ah, Al, Bh, Bl } each 128 rows x 80B (32 bf16 + pad)
#define ROWB   80
#define REGB   10240            // 128 * 80
#define STAGEB 40960
#define GT_SMEM (2 * STAGEB)

__global__ void __launch_bounds__(256, 2)
gemm_bf16(const __nv_bfloat16* __restrict__ A1h, const __nv_bfloat16* __restrict__ A1l, int K1,
          const __nv_bfloat16* __restrict__ A2h, const __nv_bfloat16* __restrict__ A2l, int K2,
          const __nv_bfloat16* __restrict__ Bh,  const __nv_bfloat16* __restrict__ Bl,  int KB,
          float* __restrict__ C, int ldC, long partStride,
          int tiles_total, const float* __restrict__ bias)
{
    extern __shared__ __align__(128) char smem[];
    const u32 sb  = smem_u32(smem);
    const int tid = threadIdx.x, lane = tid & 31, wid = tid >> 5;
    const int bm  = blockIdx.x * 128;
    const int bn  = blockIdx.y * 128;

    const int tb = (tiles_total * blockIdx.z) / gridDim.z;
    const int te = (tiles_total * (blockIdx.z + 1)) / gridDim.z;
    const int ntiles = te - tb;
    const int kbeg = tb * 32;

    // producer mapping: thread -> (row, 16-elem segment)
    const int prow = tid >> 1, pseg = tid & 1;
    const u32 pdst = (u32)(prow * ROWB + pseg * 32);

    auto issue = [&](int t, int s) {
        const int k0 = kbeg + t * 32;
        const __nv_bfloat16 *pAh, *pAl;
        if (k0 < K1) {
            long o = (long)(bm + prow) * K1 + k0 + pseg * 16;
            pAh = A1h + o; pAl = A1l + o;
        } else {
            long o = (long)(bm + prow) * K2 + (k0 - K1) + pseg * 16;
            pAh = A2h + o; pAl = A2l + o;
        }
        long ob = (long)(bn + prow) * KB + k0 + pseg * 16;
        u32 d = sb + s * STAGEB + pdst;
        cp16(d,                 pAh);     cp16(d + 16,             pAh + 8);
        cp16(d + REGB,          pAl);     cp16(d + REGB + 16,      pAl + 8);
        cp16(d + 2 * REGB,      Bh + ob); cp16(d + 2 * REGB + 16,  Bh + ob + 8);
        cp16(d + 3 * REGB,      Bl + ob); cp16(d + 3 * REGB + 16,  Bl + ob + 8);
        cp_commit();
    };

    // consumer mapping: 8 warps -> 4 (m) x 2 (n); warp tile 32x64
    const int wr = wid & 3, wc = wid >> 2;
    const u32 a_off = (u32)((wr * 32 + (lane & 15)) * ROWB + (lane >> 4) * 16);
    const u32 b_off = (u32)(2 * REGB +
                            (wc * 64 + (lane & 7) + ((lane >> 4) & 1) * 8) * ROWB +
                            ((lane >> 3) & 1) * 16);

    float acc[2][8][4];
    #pragma unroll
    for (int i = 0; i < 2; i++)
        #pragma unroll
        for (int j = 0; j < 8; j++)
            #pragma unroll
            for (int q = 0; q < 4; q++) acc[i][j][q] = 0.f;

    issue(0, 0);
    if (ntiles > 1) issue(1, 1);

    for (int t = 0; t < ntiles; t++) {
        const int s = t & 1;
        // group t complete (group t+1 may remain in flight)
        if (t + 1 < ntiles) cp_wait1(); else cp_wait0();
        __syncthreads();   // stage s fully visible to all warps

        const u32 base = sb + s * STAGEB;
        #pragma unroll
        for (int kk = 0; kk < 32; kk += 16) {
            // stage registers: keep live set small for 2-CTA occupancy.
            u32 ah[2][4], al[2][4], bx[4][4];
            #pragma unroll
            for (int mi = 0; mi < 2; mi++) {
                ldsm4(ah[mi], base + a_off + mi * (16 * ROWB) + kk * 2);
                ldsm4(al[mi], base + REGB + a_off + mi * (16 * ROWB) + kk * 2);
            }
            #pragma unroll
            for (int nj = 0; nj < 4; nj++)
                ldsm4(bx[nj], base + b_off + nj * (16 * ROWB) + kk * 2);
            // pass 1: Ah*Bh  (16 independent)
            #pragma unroll
            for (int mi = 0; mi < 2; mi++)
                #pragma unroll
                for (int nt = 0; nt < 8; nt++)
                    mma16816(acc[mi][nt], ah[mi], &bx[nt >> 1][(nt & 1) * 2]);
            // pass 2: Al*Bh  (16 independent)
            #pragma unroll
            for (int mi = 0; mi < 2; mi++)
                #pragma unroll
                for (int nt = 0; nt < 8; nt++)
                    mma16816(acc[mi][nt], al[mi], &bx[nt >> 1][(nt & 1) * 2]);
            // reload B-lo into same regs, pass 3: Ah*Bl
            #pragma unroll
            for (int nj = 0; nj < 4; nj++)
                ldsm4(bx[nj], base + REGB + b_off + nj * (16 * ROWB) + kk * 2);
            #pragma unroll
            for (int mi = 0; mi < 2; mi++)
                #pragma unroll
                for (int nt = 0; nt < 8; nt++)
                    mma16816(acc[mi][nt], ah[mi], &bx[nt >> 1][(nt & 1) * 2]);
        }
        __syncthreads();   // all warps done reading stage s
        if (t + 2 < ntiles) issue(t + 2, s);
    }

    // epilogue
    float* Cp = C + (long)blockIdx.z * partStride;
    const int gr  = bm + wr * 32 + (lane >> 2);
    const int gcb = bn + wc * 64 + (lane & 3) * 2;
    #pragma unroll
    for (int mi = 0; mi < 2; mi++)
        #pragma unroll
        for (int nt = 0; nt < 8; nt++) {
            int r0 = gr + mi * 16;
            int c  = gcb + nt * 8;
            float b0 = 0.f, b1 = 0.f;
            if (bias) { b0 = bias[c]; b1 = bias[c + 1]; }
            float2 v0 = make_float2(acc[mi][nt][0] + b0, acc[mi][nt][1] + b1);
            float2 v1 = make_float2(acc[mi][nt][2] + b0, acc[mi][nt][3] + b1);
            *(float2*)(Cp + (long)r0 * ldC + c)       = v0;
            *(float2*)(Cp + (long)(r0 + 8) * ldC + c) = v1;
        }
}

// ---------------- split-K combine + bias + residual + relu ----------------
__global__ void __launch_bounds__(256)
combine_layer(const float* __restrict__ bias,
              const float* __restrict__ xin,
              float* __restrict__ xout,
              __nv_bfloat16* __restrict__ xh,
              __nv_bfloat16* __restrict__ xl)
{
    const int i = blockIdx.x * 256 + threadIdx.x;      // over BSZ*DIM/4
    const float4* p = (const float4*)g_part;
    const int Q = BSZ * DIM / 4;
    float4 acc = p[i];
    #pragma unroll
    for (int q = 1; q < NSPLIT; q++) {
        float4 v = p[i + q * Q];
        acc.x += v.x; acc.y += v.y; acc.z += v.z; acc.w += v.w;
    }
    float4 xi = ((const float4*)xin)[i];
    float4 bb = ((const float4*)bias)[i & 31];
    float4 o;
    o.x = fmaxf(acc.x + xi.x + bb.x, 0.f);
    o.y = fmaxf(acc.y + xi.y + bb.y, 0.f);
    o.z = fmaxf(acc.z + xi.z + bb.z, 0.f);
    o.w = fmaxf(acc.w + xi.w + bb.w, 0.f);
    ((float4*)xout)[i] = o;

    __nv_bfloat16 hx, lx, hy, ly, hz, lz, hw, lw;
    split_bf16(o.x, hx, lx); split_bf16(o.y, hy, ly);
    split_bf16(o.z, hz, lz); split_bf16(o.w, hw, lw);
    __nv_bfloat162* ph = (__nv_bfloat162*)xh;
    __nv_bfloat162* pl = (__nv_bfloat162*)xl;
    ph[2 * i]     = __nv_bfloat162(hx, hy);
    ph[2 * i + 1] = __nv_bfloat162(hz, hw);
    pl[2 * i]     = __nv_bfloat162(lx, ly);
    pl[2 * i + 1] = __nv_bfloat162(lz, lw);
}

// ---------------- attention (L=2, one warp per head) ----------------
__global__ void __launch_bounds__(128)
attn_kernel()
{
    const int b = blockIdx.x;
    const int h = threadIdx.x >> 5;
    const int d = threadIdx.x & 31;

    const float* p0 = g_qkv + (long)b * NQKV + h * 32 + d;
    const float* p1 = p0 + (long)BSZ * NQKV;
    float q0 = p0[0], k0 = p0[128], v0 = p0[256];
    float q1 = p1[0], k1 = p1[128], v1 = p1[256];

    float s00 = q0 * k0, s01 = q0 * k1, s10 = q1 * k0, s11 = q1 * k1;
    #pragma unroll
    for (int o = 16; o; o >>= 1) {
        s00 += __shfl_xor_sync(0xffffffffu, s00, o);
        s01 += __shfl_xor_sync(0xffffffffu, s01, o);
        s10 += __shfl_xor_sync(0xffffffffu, s10, o);
        s11 += __shfl_xor_sync(0xffffffffu, s11, o);
    }
    const float inv = 0.17677669529663687f;  // 1/sqrt(32)
    s00 *= inv; s01 *= inv; s10 *= inv; s11 *= inv;

    float m0 = fmaxf(s00, s01), m1 = fmaxf(s10, s11);
    float e00 = expf(s00 - m0), e01 = expf(s01 - m0);
    float e10 = expf(s10 - m1), e11 = expf(s11 - m1);
    float o0 = (e00 * v0 + e01 * v1) / (e00 + e01);
    float o1 = (e10 * v0 + e11 * v1) / (e10 + e11);

    float v = 0.5f * (o0 + o1);
    __nv_bfloat16 hh, ll; split_bf16(v, hh, ll);
    g_oh[(long)b * DIM + h * 32 + d] = hh;
    g_ol[(long)b * DIM + h * 32 + d] = ll;
}

// ---------------- host launcher ----------------
extern "C" void kernel_launch(void* const* d_in, const int* in_sizes, int n_in,
                              void* d_out, int out_size)
{
    const int*   drug = (const int*)  d_in[0];
    const int*   adjE = (const int*)  d_in[1];
    const int*   adjR = (const int*)  d_in[2];
    const float* ew   = (const float*)d_in[3];
    const float* E    = (const float*)d_in[4];
    const float* Wrel = (const float*)d_in[5];
    const float* resW = (const float*)d_in[6];
    const float* resb = (const float*)d_in[7];
    const float* inW  = (const float*)d_in[8];
    const float* inB  = (const float*)d_in[9];
    const float* outW = (const float*)d_in[10];
    const float* outB = (const float*)d_in[11];

    __nv_bfloat16 *aggh, *aggl, *xh, *xl, *oh, *ol, *Wth, *Wtl, *inh, *inl, *outh, *outl;
    float *xf, *qkv, *part;
    cudaGetSymbolAddress((void**)&aggh, g_aggh);
    cudaGetSymbolAddress((void**)&aggl, g_aggl);
    cudaGetSymbolAddress((void**)&xf,   g_x);
    cudaGetSymbolAddress((void**)&xh,   g_xh);
    cudaGetSymbolAddress((void**)&xl,   g_xl);
    cudaGetSymbolAddress((void**)&qkv,  g_qkv);
    cudaGetSymbolAddress((void**)&oh,   g_oh);
    cudaGetSymbolAddress((void**)&ol,   g_ol);
    cudaGetSymbolAddress((void**)&Wth,  g_Wth);
    cudaGetSymbolAddress((void**)&Wtl,  g_Wtl);
    cudaGetSymbolAddress((void**)&inh,  g_inh);
    cudaGetSymbolAddress((void**)&inl,  g_inl);
    cudaGetSymbolAddress((void**)&outh, g_outh);
    cudaGetSymbolAddress((void**)&outl, g_outl);
    cudaGetSymbolAddress((void**)&part, g_part);

    cudaFuncSetAttribute(gemm_bf16, cudaFuncAttributeMaxDynamicSharedMemorySize, GT_SMEM);

    transpose_wrel<<<dim3(4, 4, 32), dim3(32, 8)>>>(Wrel);
    prep_rest<<<(2 * DIM * DIM + NQKV * DIM + DIM * DIM + 255) / 256, 256>>>(resW, inW, outW);
    agg_kernel<<<BSZ, 128>>>(drug, adjE, adjR, ew, E);

    // layer 0: part = split-K((agg|x0) @ Wcat0^T); x1 = relu(sum + b0 + x0)
    gemm_bf16<<<dim3(BSZ / 128, 1, NSPLIT), 256, GT_SMEM>>>(
        aggh, aggl, KAGG, xh, xl, DIM, Wth, Wtl, KCAT,
        part, DIM, (long)BSZ * DIM, LAYER_TILES, nullptr);
    combine_layer<<<BSZ * DIM / 4 / 256, 256>>>(
        resb, xf, xf + BSZ * DIM, xh + BSZ * DIM, xl + BSZ * DIM);

    // layer 1
    gemm_bf16<<<dim3(BSZ / 128, 1, NSPLIT), 256, GT_SMEM>>>(
        aggh, aggl, KAGG, xh + BSZ * DIM, xl + BSZ * DIM, DIM,
        Wth + DIM * KCAT, Wtl + DIM * KCAT, KCAT,
        part, DIM, (long)BSZ * DIM, LAYER_TILES, nullptr);
    combine_layer<<<BSZ * DIM / 4 / 256, 256>>>(
        resb + DIM, xf + BSZ * DIM, xf + 2 * BSZ * DIM,
        xh + 2 * BSZ * DIM, xl + 2 * BSZ * DIM);

    // qkv for both layer outputs: M=8192 (x1,x2 contiguous), N=384, K=128
    gemm_bf16<<<dim3(2 * BSZ / 128, NQKV / 128, 1), 256, GT_SMEM>>>(
        xh + BSZ * DIM, xl + BSZ * DIM, DIM, nullptr, nullptr, 0,
        inh, inl, DIM, qkv, NQKV, 0, 4, inB);

    attn_kernel<<<BSZ, 128>>>();

    // out projection: M=4096, N=128, K=128 -> d_out
    gemm_bf16<<<dim3(BSZ / 128, 1, 1), 256, GT_SMEM>>>(
        oh, ol, DIM, nullptr, nullptr, 0,
        outh, outl, DIM, (float*)d_out, DIM, 0, 4, outB);
}

// round 10
// speedup vs baseline: 1.3157x; 1.1830x over previous
#include <cuda_runtime.h>
#include <cuda_fp16.h>
#include <math.h>
#include <stdint.h>

typedef unsigned long long u64;
typedef unsigned int u32;

// ---------------- problem constants ----------------
#define BSZ   4096
#define DIM   128
#define KNBR  64
#define NREL  16
#define KAGG  2048          // NREL * DIM
#define KCAT  2176          // KAGG + DIM
#define NQKV  384
#define NSPLIT 8            // split-K for layer GEMMs (68 tiles -> 8..9 each)
#define LAYER_TILES 68      // KCAT / 32

// ---------------- device scratch ----------------
__device__ __half g_aggh[BSZ * KAGG];
__device__ __half g_aggl[BSZ * KAGG];
__device__ float  g_x   [3][BSZ * DIM];        // fp32 x0,x1 (residuals)
__device__ __half g_xh  [3 * BSZ * DIM];       // x0,x1,x2 hi
__device__ __half g_xl  [3 * BSZ * DIM];       // x0,x1,x2 lo
__device__ float  g_qkv [2 * BSZ * NQKV];
__device__ __half g_oh  [BSZ * DIM];
__device__ __half g_ol  [BSZ * DIM];
__device__ __half g_Wt  [2 * DIM * KCAT];      // B for layer gemm, [l][e][k], fp16
__device__ __half g_in  [NQKV * DIM];          // in_proj_w fp16
__device__ __half g_out [DIM * DIM];           // out_proj_w fp16
__device__ float  g_part[NSPLIT * BSZ * DIM];

// ================= PTX helpers =================
__device__ __forceinline__ u32 smem_u32(const void* p) {
    u32 a; asm("{ .reg .u64 t; cvta.to.shared.u64 t, %1; cvt.u32.u64 %0, t; }" : "=r"(a) : "l"(p));
    return a;
}
__device__ __forceinline__ void cp16(u32 s, const void* g) {
    asm volatile("cp.async.cg.shared.global [%0], [%1], 16;" :: "r"(s), "l"(g));
}
__device__ __forceinline__ void cp_commit() {
    asm volatile("cp.async.commit_group;" ::: "memory");
}
__device__ __forceinline__ void cp_wait0() {
    asm volatile("cp.async.wait_group 0;" ::: "memory");
}
__device__ __forceinline__ void cp_wait1() {
    asm volatile("cp.async.wait_group 1;" ::: "memory");
}
__device__ __forceinline__ void ldsm4(u32* r, u32 addr) {
    asm volatile("ldmatrix.sync.aligned.m8n8.x4.shared.b16 {%0,%1,%2,%3}, [%4];"
                 : "=r"(r[0]), "=r"(r[1]), "=r"(r[2]), "=r"(r[3]) : "r"(addr));
}
__device__ __forceinline__ void mma16816(float* c, const u32* a, const u32* b) {
    asm volatile(
        "mma.sync.aligned.m16n8k16.row.col.f32.f16.f16.f32 "
        "{%0,%1,%2,%3}, {%4,%5,%6,%7}, {%8,%9}, {%0,%1,%2,%3};"
        : "+f"(c[0]), "+f"(c[1]), "+f"(c[2]), "+f"(c[3])
        : "r"(a[0]), "r"(a[1]), "r"(a[2]), "r"(a[3]), "r"(b[0]), "r"(b[1]));
}
__device__ __forceinline__ void split_f16(float v, __half& h, __half& l) {
    h = __float2half_rn(v);
    l = __float2half_rn(v - __half2float(h));
}

// ================= prep kernels =================
// W_rel[l,r,d,e] -> B[l][e][r*128+d]  (fp16)
__global__ void transpose_wrel(const float* __restrict__ Wrel)
{
    __shared__ float tile[32][33];
    const int mat = blockIdx.z;           // l*16 + r
    const int l = mat >> 4, r = mat & 15;
    const int tx = threadIdx.x, ty = threadIdx.y;
    const float* src = Wrel + (long)mat * 16384;
    int e_in = blockIdx.x * 32 + tx;
    #pragma unroll
    for (int i = 0; i < 4; i++) {
        int d = blockIdx.y * 32 + ty + i * 8;
        tile[ty + i * 8][tx] = src[d * 128 + e_in];
    }
    __syncthreads();
    const long base = (long)l * (DIM * KCAT);
    #pragma unroll
    for (int i = 0; i < 4; i++) {
        int e = blockIdx.x * 32 + ty + i * 8;
        int d = blockIdx.y * 32 + tx;
        g_Wt[base + (long)e * KCAT + r * 128 + d] = __float2half_rn(tile[tx][ty + i * 8]);
    }
}

// res_W[l,e,d] -> B[l][e][2048+d]; plus inW / outW fp16 conversion
__global__ void prep_rest(const float* __restrict__ resW,
                          const float* __restrict__ inW,
                          const float* __restrict__ outW)
{
    int i = blockIdx.x * 256 + threadIdx.x;
    const int NR = 2 * DIM * DIM;         // 32768
    const int NI = NQKV * DIM;            // 49152
    const int NO = DIM * DIM;             // 16384
    if (i < NR) {
        int l = i >> 14, e = (i >> 7) & 127, d = i & 127;
        g_Wt[(long)l * (DIM * KCAT) + (long)e * KCAT + 2048 + d] = __float2half_rn(resW[i]);
    } else if (i < NR + NI) {
        int t = i - NR;
        g_in[t] = __float2half_rn(inW[t]);
    } else if (i < NR + NI + NO) {
        int t = i - NR - NI;
        g_out[t] = __float2half_rn(outW[t]);
    }
}

// ---------------- agg: relation scatter + x0 gather (fp16 hi/lo outputs) ----
__global__ void __launch_bounds__(128)
agg_kernel(const int* __restrict__ drug,
           const int* __restrict__ adjE,
           const int* __restrict__ adjR,
           const float* __restrict__ ew,
           const float* __restrict__ E)
{
    __shared__ float s[NREL * DIM];
    __shared__ int   se[KNBR];
    __shared__ int   sr[KNBR];
    __shared__ float sw[KNBR];

    const int b = blockIdx.x;
    const int d = threadIdx.x;

    #pragma unroll
    for (int r = 0; r < NREL; r++) s[r * DIM + d] = 0.f;

    if (d < KNBR) {
        se[d] = adjE[b * KNBR + d];
        sr[d] = adjR[b * KNBR + d];
        sw[d] = ew  [b * KNBR + d];
    }
    {
        float v = E[(long)drug[b] * DIM + d];
        g_x[0][b * DIM + d] = v;
        __half h, lo; split_f16(v, h, lo);
        g_xh[b * DIM + d] = h; g_xl[b * DIM + d] = lo;
    }
    __syncthreads();

    #pragma unroll 1
    for (int k = 0; k < KNBR; k += 4) {
        float e0 = E[(long)se[k + 0] * DIM + d];
        float e1 = E[(long)se[k + 1] * DIM + d];
        float e2 = E[(long)se[k + 2] * DIM + d];
        float e3 = E[(long)se[k + 3] * DIM + d];
        s[sr[k + 0] * DIM + d] += sw[k + 0] * e0;
        s[sr[k + 1] * DIM + d] += sw[k + 1] * e1;
        s[sr[k + 2] * DIM + d] += sw[k + 2] * e2;
        s[sr[k + 3] * DIM + d] += sw[k + 3] * e3;
    }
    const long ao = (long)b * KAGG;
    #pragma unroll
    for (int r = 0; r < NREL; r++) {
        float v = s[r * DIM + d];
        __half h, lo; split_f16(v, h, lo);
        g_aggh[ao + r * DIM + d] = h;
        g_aggl[ao + r * DIM + d] = lo;
    }
}

// ================= fp16 hi/lo 2-pass tensor-core GEMM =================
// 256 threads / 8 warps; CTA tile 128x128; warp tile 32x64; 2 CTAs/SM.
// C[m,n] = sum_k A[m,k]*B[n,k]; A = [A1 | A2] hi/lo fp16 pairs; B single fp16.
// k-range per blockIdx.z: tiles [tiles_total*z/Z, tiles_total*(z+1)/Z).
// SMEM: 2 stages x { Ah, Al, B } each 128 rows x 80B (32 fp16 + pad)
#define ROWB   80
#define REGB   10240            // 128 * 80
#define STAGEB 30720            // 3 * REGB
#define GT_SMEM (2 * STAGEB)

__global__ void __launch_bounds__(256, 2)
gemm_f16(const __half* __restrict__ A1h, const __half* __restrict__ A1l, int K1,
         const __half* __restrict__ A2h, const __half* __restrict__ A2l, int K2,
         const __half* __restrict__ Bm, int KB,
         float* __restrict__ C, int ldC, long partStride,
         int tiles_total, const float* __restrict__ bias)
{
    extern __shared__ __align__(128) char smem[];
    const u32 sb  = smem_u32(smem);
    const int tid = threadIdx.x, lane = tid & 31, wid = tid >> 5;
    const int bm  = blockIdx.x * 128;
    const int bn  = blockIdx.y * 128;

    const int tb = (tiles_total * blockIdx.z) / gridDim.z;
    const int te = (tiles_total * (blockIdx.z + 1)) / gridDim.z;
    const int ntiles = te - tb;
    const int kbeg = tb * 32;

    // producer mapping: thread -> (row, 16-elem segment)
    const int prow = tid >> 1, pseg = tid & 1;
    const u32 pdst = (u32)(prow * ROWB + pseg * 32);

    auto issue = [&](int t, int s) {
        const int k0 = kbeg + t * 32;
        const __half *pAh, *pAl;
        if (k0 < K1) {
            long o = (long)(bm + prow) * K1 + k0 + pseg * 16;
            pAh = A1h + o; pAl = A1l + o;
        } else {
            long o = (long)(bm + prow) * K2 + (k0 - K1) + pseg * 16;
            pAh = A2h + o; pAl = A2l + o;
        }
        long ob = (long)(bn + prow) * KB + k0 + pseg * 16;
        u32 d = sb + s * STAGEB + pdst;
        cp16(d,            pAh);      cp16(d + 16,            pAh + 8);
        cp16(d + REGB,     pAl);      cp16(d + REGB + 16,     pAl + 8);
        cp16(d + 2 * REGB, Bm + ob);  cp16(d + 2 * REGB + 16, Bm + ob + 8);
        cp_commit();
    };

    // consumer mapping: 8 warps -> 4 (m) x 2 (n); warp tile 32x64
    const int wr = wid & 3, wc = wid >> 2;
    const u32 a_off = (u32)((wr * 32 + (lane & 15)) * ROWB + (lane >> 4) * 16);
    const u32 b_off = (u32)(2 * REGB +
                            (wc * 64 + (lane & 7) + ((lane >> 4) & 1) * 8) * ROWB +
                            ((lane >> 3) & 1) * 16);

    float acc[2][8][4];
    #pragma unroll
    for (int i = 0; i < 2; i++)
        #pragma unroll
        for (int j = 0; j < 8; j++)
            #pragma unroll
            for (int q = 0; q < 4; q++) acc[i][j][q] = 0.f;

    issue(0, 0);
    if (ntiles > 1) issue(1, 1);

    for (int t = 0; t < ntiles; t++) {
        const int s = t & 1;
        if (t + 1 < ntiles) cp_wait1(); else cp_wait0();
        __syncthreads();   // stage s fully visible to all warps

        const u32 base = sb + s * STAGEB;
        #pragma unroll
        for (int kk = 0; kk < 32; kk += 16) {
            u32 ah[2][4], al[2][4], bx[4][4];
            #pragma unroll
            for (int mi = 0; mi < 2; mi++) {
                ldsm4(ah[mi], base + a_off + mi * (16 * ROWB) + kk * 2);
                ldsm4(al[mi], base + REGB + a_off + mi * (16 * ROWB) + kk * 2);
            }
            #pragma unroll
            for (int nj = 0; nj < 4; nj++)
                ldsm4(bx[nj], base + b_off + nj * (16 * ROWB) + kk * 2);
            // pass 1: Ah*B  (16 independent)
            #pragma unroll
            for (int mi = 0; mi < 2; mi++)
                #pragma unroll
                for (int nt = 0; nt < 8; nt++)
                    mma16816(acc[mi][nt], ah[mi], &bx[nt >> 1][(nt & 1) * 2]);
            // pass 2: Al*B  (16 independent)
            #pragma unroll
            for (int mi = 0; mi < 2; mi++)
                #pragma unroll
                for (int nt = 0; nt < 8; nt++)
                    mma16816(acc[mi][nt], al[mi], &bx[nt >> 1][(nt & 1) * 2]);
        }
        __syncthreads();   // all warps done reading stage s
        if (t + 2 < ntiles) issue(t + 2, s);
    }

    // epilogue
    float* Cp = C + (long)blockIdx.z * partStride;
    const int gr  = bm + wr * 32 + (lane >> 2);
    const int gcb = bn + wc * 64 + (lane & 3) * 2;
    #pragma unroll
    for (int mi = 0; mi < 2; mi++)
        #pragma unroll
        for (int nt = 0; nt < 8; nt++) {
            int r0 = gr + mi * 16;
            int c  = gcb + nt * 8;
            float b0 = 0.f, b1 = 0.f;
            if (bias) { b0 = bias[c]; b1 = bias[c + 1]; }
            float2 v0 = make_float2(acc[mi][nt][0] + b0, acc[mi][nt][1] + b1);
            float2 v1 = make_float2(acc[mi][nt][2] + b0, acc[mi][nt][3] + b1);
            *(float2*)(Cp + (long)r0 * ldC + c)       = v0;
            *(float2*)(Cp + (long)(r0 + 8) * ldC + c) = v1;
        }
}

// ---------------- split-K combine + bias + residual + relu ----------------
__global__ void __launch_bounds__(256)
combine_layer(const float* __restrict__ bias,
              const float* __restrict__ xin,
              float* __restrict__ xout,
              __half* __restrict__ xh,
              __half* __restrict__ xl)
{
    const int i = blockIdx.x * 256 + threadIdx.x;      // over BSZ*DIM/4
    const float4* p = (const float4*)g_part;
    const int Q = BSZ * DIM / 4;
    float4 acc = p[i];
    #pragma unroll
    for (int q = 1; q < NSPLIT; q++) {
        float4 v = p[i + q * Q];
        acc.x += v.x; acc.y += v.y; acc.z += v.z; acc.w += v.w;
    }
    float4 xi = ((const float4*)xin)[i];
    float4 bb = ((const float4*)bias)[i & 31];
    float4 o;
    o.x = fmaxf(acc.x + xi.x + bb.x, 0.f);
    o.y = fmaxf(acc.y + xi.y + bb.y, 0.f);
    o.z = fmaxf(acc.z + xi.z + bb.z, 0.f);
    o.w = fmaxf(acc.w + xi.w + bb.w, 0.f);
    ((float4*)xout)[i] = o;

    __half hx, lx, hy, ly, hz, lz, hw, lw;
    split_f16(o.x, hx, lx); split_f16(o.y, hy, ly);
    split_f16(o.z, hz, lz); split_f16(o.w, hw, lw);
    __half2* ph = (__half2*)xh;
    __half2* pl = (__half2*)xl;
    ph[2 * i]     = __halves2half2(hx, hy);
    ph[2 * i + 1] = __halves2half2(hz, hw);
    pl[2 * i]     = __halves2half2(lx, ly);
    pl[2 * i + 1] = __halves2half2(lz, lw);
}

// ---------------- attention (L=2, one warp per head) ----------------
__global__ void __launch_bounds__(128)
attn_kernel()
{
    const int b = blockIdx.x;
    const int h = threadIdx.x >> 5;
    const int d = threadIdx.x & 31;

    const float* p0 = g_qkv + (long)b * NQKV + h * 32 + d;
    const float* p1 = p0 + (long)BSZ * NQKV;
    float q0 = p0[0], k0 = p0[128], v0 = p0[256];
    float q1 = p1[0], k1 = p1[128], v1 = p1[256];

    float s00 = q0 * k0, s01 = q0 * k1, s10 = q1 * k0, s11 = q1 * k1;
    #pragma unroll
    for (int o = 16; o; o >>= 1) {
        s00 += __shfl_xor_sync(0xffffffffu, s00, o);
        s01 += __shfl_xor_sync(0xffffffffu, s01, o);
        s10 += __shfl_xor_sync(0xffffffffu, s10, o);
        s11 += __shfl_xor_sync(0xffffffffu, s11, o);
    }
    const float inv = 0.17677669529663687f;  // 1/sqrt(32)
    s00 *= inv; s01 *= inv; s10 *= inv; s11 *= inv;

    float m0 = fmaxf(s00, s01), m1 = fmaxf(s10, s11);
    float e00 = expf(s00 - m0), e01 = expf(s01 - m0);
    float e10 = expf(s10 - m1), e11 = expf(s11 - m1);
    float o0 = (e00 * v0 + e01 * v1) / (e00 + e01);
    float o1 = (e10 * v0 + e11 * v1) / (e10 + e11);

    float v = 0.5f * (o0 + o1);
    __half hh, ll; split_f16(v, hh, ll);
    g_oh[(long)b * DIM + h * 32 + d] = hh;
    g_ol[(long)b * DIM + h * 32 + d] = ll;
}

// ---------------- host launcher ----------------
extern "C" void kernel_launch(void* const* d_in, const int* in_sizes, int n_in,
                              void* d_out, int out_size)
{
    const int*   drug = (const int*)  d_in[0];
    const int*   adjE = (const int*)  d_in[1];
    const int*   adjR = (const int*)  d_in[2];
    const float* ew   = (const float*)d_in[3];
    const float* E    = (const float*)d_in[4];
    const float* Wrel = (const float*)d_in[5];
    const float* resW = (const float*)d_in[6];
    const float* resb = (const float*)d_in[7];
    const float* inW  = (const float*)d_in[8];
    const float* inB  = (const float*)d_in[9];
    const float* outW = (const float*)d_in[10];
    const float* outB = (const float*)d_in[11];

    __half *aggh, *aggl, *xh, *xl, *oh, *ol, *Wt, *inw, *outw;
    float *xf, *qkv, *part;
    cudaGetSymbolAddress((void**)&aggh, g_aggh);
    cudaGetSymbolAddress((void**)&aggl, g_aggl);
    cudaGetSymbolAddress((void**)&xf,   g_x);
    cudaGetSymbolAddress((void**)&xh,   g_xh);
    cudaGetSymbolAddress((void**)&xl,   g_xl);
    cudaGetSymbolAddress((void**)&qkv,  g_qkv);
    cudaGetSymbolAddress((void**)&oh,   g_oh);
    cudaGetSymbolAddress((void**)&ol,   g_ol);
    cudaGetSymbolAddress((void**)&Wt,   g_Wt);
    cudaGetSymbolAddress((void**)&inw,  g_in);
    cudaGetSymbolAddress((void**)&outw, g_out);
    cudaGetSymbolAddress((void**)&part, g_part);

    cudaFuncSetAttribute(gemm_f16, cudaFuncAttributeMaxDynamicSharedMemorySize, GT_SMEM);

    transpose_wrel<<<dim3(4, 4, 32), dim3(32, 8)>>>(Wrel);
    prep_rest<<<(2 * DIM * DIM + NQKV * DIM + DIM * DIM + 255) / 256, 256>>>(resW, inW, outW);
    agg_kernel<<<BSZ, 128>>>(drug, adjE, adjR, ew, E);

    // layer 0: part = split-K((agg|x0) @ Wcat0^T); x1 = relu(sum + b0 + x0)
    gemm_f16<<<dim3(BSZ / 128, 1, NSPLIT), 256, GT_SMEM>>>(
        aggh, aggl, KAGG, xh, xl, DIM, Wt, KCAT,
        part, DIM, (long)BSZ * DIM, LAYER_TILES, nullptr);
    combine_layer<<<BSZ * DIM / 4 / 256, 256>>>(
        resb, xf, xf + BSZ * DIM, xh + BSZ * DIM, xl + BSZ * DIM);

    // layer 1
    gemm_f16<<<dim3(BSZ / 128, 1, NSPLIT), 256, GT_SMEM>>>(
        aggh, aggl, KAGG, xh + BSZ * DIM, xl + BSZ * DIM, DIM,
        Wt + DIM * KCAT, KCAT,
        part, DIM, (long)BSZ * DIM, LAYER_TILES, nullptr);
    combine_layer<<<BSZ * DIM / 4 / 256, 256>>>(
        resb + DIM, xf + BSZ * DIM, xf + 2 * BSZ * DIM,
        xh + 2 * BSZ * DIM, xl + 2 * BSZ * DIM);

    // qkv for both layer outputs: M=8192 (x1,x2 contiguous), N=384, K=128
    gemm_f16<<<dim3(2 * BSZ / 128, NQKV / 128, 1), 256, GT_SMEM>>>(
        xh + BSZ * DIM, xl + BSZ * DIM, DIM, nullptr, nullptr, 0,
        inw, DIM, qkv, NQKV, 0, 4, inB);

    attn_kernel<<<BSZ, 128>>>();

    // out projection: M=4096, N=128, K=128 -> d_out
    gemm_f16<<<dim3(BSZ / 128, 1, 1), 256, GT_SMEM>>>(
        oh, ol, DIM, nullptr, nullptr, 0,
        outw, DIM, (float*)d_out, DIM, 0, 4, outB);
}

// round 11
// speedup vs baseline: 1.5353x; 1.1669x over previous
#include <cuda_runtime.h>
#include <cuda_fp16.h>
#include <math.h>
#include <stdint.h>

typedef unsigned long long u64;
typedef unsigned int u32;

// ---------------- problem constants ----------------
#define BSZ   4096
#define DIM   128
#define KNBR  64
#define NREL  16
#define KAGG  2048          // NREL * DIM
#define KCAT  2176          // KAGG + DIM
#define NQKV  384
#define NSPLIT 8            // split-K for layer GEMMs (68 tiles -> 8..9 each)
#define LAYER_TILES 68      // KCAT / 32

// ---------------- device scratch ----------------
__device__ __half g_aggh[BSZ * KAGG];
__device__ float  g_x   [3][BSZ * DIM];        // fp32 x0,x1 (residuals)
__device__ __half g_xh  [3 * BSZ * DIM];       // x0,x1,x2 hi
__device__ __half g_xl  [3 * BSZ * DIM];       // x1,x2 lo (x0 slice unused)
__device__ float  g_qkv [2 * BSZ * NQKV];
__device__ __half g_oh  [BSZ * DIM];
__device__ __half g_ol  [BSZ * DIM];
__device__ __half g_Wt  [2 * DIM * KCAT];      // B for layer gemm, [l][e][k], fp16
__device__ __half g_in  [NQKV * DIM];          // in_proj_w fp16
__device__ __half g_out [DIM * DIM];           // out_proj_w fp16
__device__ float  g_part[NSPLIT * BSZ * DIM];

// ================= PTX helpers =================
__device__ __forceinline__ u32 smem_u32(const void* p) {
    u32 a; asm("{ .reg .u64 t; cvta.to.shared.u64 t, %1; cvt.u32.u64 %0, t; }" : "=r"(a) : "l"(p));
    return a;
}
__device__ __forceinline__ void cp16(u32 s, const void* g) {
    asm volatile("cp.async.cg.shared.global [%0], [%1], 16;" :: "r"(s), "l"(g));
}
__device__ __forceinline__ void cp_commit() {
    asm volatile("cp.async.commit_group;" ::: "memory");
}
__device__ __forceinline__ void cp_wait0() {
    asm volatile("cp.async.wait_group 0;" ::: "memory");
}
__device__ __forceinline__ void cp_wait1() {
    asm volatile("cp.async.wait_group 1;" ::: "memory");
}
__device__ __forceinline__ void ldsm4(u32* r, u32 addr) {
    asm volatile("ldmatrix.sync.aligned.m8n8.x4.shared.b16 {%0,%1,%2,%3}, [%4];"
                 : "=r"(r[0]), "=r"(r[1]), "=r"(r[2]), "=r"(r[3]) : "r"(addr));
}
__device__ __forceinline__ void mma16816(float* c, const u32* a, const u32* b) {
    asm volatile(
        "mma.sync.aligned.m16n8k16.row.col.f32.f16.f16.f32 "
        "{%0,%1,%2,%3}, {%4,%5,%6,%7}, {%8,%9}, {%0,%1,%2,%3};"
        : "+f"(c[0]), "+f"(c[1]), "+f"(c[2]), "+f"(c[3])
        : "r"(a[0]), "r"(a[1]), "r"(a[2]), "r"(a[3]), "r"(b[0]), "r"(b[1]));
}
__device__ __forceinline__ void split_f16(float v, __half& h, __half& l) {
    h = __float2half_rn(v);
    l = __float2half_rn(v - __half2float(h));
}

// ================= prep kernels =================
// W_rel[l,r,d,e] -> B[l][e][r*128+d]  (fp16)
__global__ void transpose_wrel(const float* __restrict__ Wrel)
{
    __shared__ float tile[32][33];
    const int mat = blockIdx.z;           // l*16 + r
    const int l = mat >> 4, r = mat & 15;
    const int tx = threadIdx.x, ty = threadIdx.y;
    const float* src = Wrel + (long)mat * 16384;
    int e_in = blockIdx.x * 32 + tx;
    #pragma unroll
    for (int i = 0; i < 4; i++) {
        int d = blockIdx.y * 32 + ty + i * 8;
        tile[ty + i * 8][tx] = src[d * 128 + e_in];
    }
    __syncthreads();
    const long base = (long)l * (DIM * KCAT);
    #pragma unroll
    for (int i = 0; i < 4; i++) {
        int e = blockIdx.x * 32 + ty + i * 8;
        int d = blockIdx.y * 32 + tx;
        g_Wt[base + (long)e * KCAT + r * 128 + d] = __float2half_rn(tile[tx][ty + i * 8]);
    }
}

// res_W[l,e,d] -> B[l][e][2048+d]; plus inW / outW fp16 conversion
__global__ void prep_rest(const float* __restrict__ resW,
                          const float* __restrict__ inW,
                          const float* __restrict__ outW)
{
    int i = blockIdx.x * 256 + threadIdx.x;
    const int NR = 2 * DIM * DIM;         // 32768
    const int NI = NQKV * DIM;            // 49152
    const int NO = DIM * DIM;             // 16384
    if (i < NR) {
        int l = i >> 14, e = (i >> 7) & 127, d = i & 127;
        g_Wt[(long)l * (DIM * KCAT) + (long)e * KCAT + 2048 + d] = __float2half_rn(resW[i]);
    } else if (i < NR + NI) {
        int t = i - NR;
        g_in[t] = __float2half_rn(inW[t]);
    } else if (i < NR + NI + NO) {
        int t = i - NR - NI;
        g_out[t] = __float2half_rn(outW[t]);
    }
}

// ---------------- agg: relation scatter + x0 gather (fp16 hi outputs) ------
__global__ void __launch_bounds__(128)
agg_kernel(const int* __restrict__ drug,
           const int* __restrict__ adjE,
           const int* __restrict__ adjR,
           const float* __restrict__ ew,
           const float* __restrict__ E)
{
    __shared__ float s[NREL * DIM];
    __shared__ int   se[KNBR];
    __shared__ int   sr[KNBR];
    __shared__ float sw[KNBR];

    const int b = blockIdx.x;
    const int d = threadIdx.x;

    #pragma unroll
    for (int r = 0; r < NREL; r++) s[r * DIM + d] = 0.f;

    if (d < KNBR) {
        se[d] = adjE[b * KNBR + d];
        sr[d] = adjR[b * KNBR + d];
        sw[d] = ew  [b * KNBR + d];
    }
    {
        float v = E[(long)drug[b] * DIM + d];
        g_x[0][b * DIM + d] = v;
        g_xh[b * DIM + d] = __float2half_rn(v);
    }
    __syncthreads();

    #pragma unroll 1
    for (int k = 0; k < KNBR; k += 4) {
        float e0 = E[(long)se[k + 0] * DIM + d];
        float e1 = E[(long)se[k + 1] * DIM + d];
        float e2 = E[(long)se[k + 2] * DIM + d];
        float e3 = E[(long)se[k + 3] * DIM + d];
        s[sr[k + 0] * DIM + d] += sw[k + 0] * e0;
        s[sr[k + 1] * DIM + d] += sw[k + 1] * e1;
        s[sr[k + 2] * DIM + d] += sw[k + 2] * e2;
        s[sr[k + 3] * DIM + d] += sw[k + 3] * e3;
    }
    const long ao = (long)b * KAGG;
    #pragma unroll
    for (int r = 0; r < NREL; r++)
        g_aggh[ao + r * DIM + d] = __float2half_rn(s[r * DIM + d]);
}

// ================= fp16 hi/lo tensor-core GEMM (1 or 2 passes) =============
// 256 threads / 8 warps; CTA tile 128x128; warp tile 32x64; 2 CTAs/SM.
// C[m,n] = sum_k A[m,k]*B[n,k]; A = [A1 | A2] fp16 (optional lo limbs); B fp16.
// npass==2 adds the Al*B correction pass (A1l/A2l must be valid).
// k-range per blockIdx.z: tiles [tiles_total*z/Z, tiles_total*(z+1)/Z).
// SMEM: 2 stages x { Ah, Al, B } each 128 rows x 80B (32 fp16 + pad)
#define ROWB   80
#define REGB   10240            // 128 * 80
#define STAGEB 30720            // 3 * REGB
#define GT_SMEM (2 * STAGEB)

__global__ void __launch_bounds__(256, 2)
gemm_f16(const __half* __restrict__ A1h, const __half* __restrict__ A1l, int K1,
         const __half* __restrict__ A2h, const __half* __restrict__ A2l, int K2,
         const __half* __restrict__ Bm, int KB,
         float* __restrict__ C, int ldC, long partStride,
         int tiles_total, const float* __restrict__ bias, int npass)
{
    extern __shared__ __align__(128) char smem[];
    const u32 sb  = smem_u32(smem);
    const int tid = threadIdx.x, lane = tid & 31, wid = tid >> 5;
    const int bm  = blockIdx.x * 128;
    const int bn  = blockIdx.y * 128;

    const int tb = (tiles_total * blockIdx.z) / gridDim.z;
    const int te = (tiles_total * (blockIdx.z + 1)) / gridDim.z;
    const int ntiles = te - tb;
    const int kbeg = tb * 32;

    // producer mapping: thread -> (row, 16-elem segment)
    const int prow = tid >> 1, pseg = tid & 1;
    const u32 pdst = (u32)(prow * ROWB + pseg * 32);

    auto issue = [&](int t, int s) {
        const int k0 = kbeg + t * 32;
        const __half *pAh, *pAl;
        if (k0 < K1) {
            long o = (long)(bm + prow) * K1 + k0 + pseg * 16;
            pAh = A1h + o; pAl = A1l ? A1l + o : nullptr;
        } else {
            long o = (long)(bm + prow) * K2 + (k0 - K1) + pseg * 16;
            pAh = A2h + o; pAl = A2l ? A2l + o : nullptr;
        }
        long ob = (long)(bn + prow) * KB + k0 + pseg * 16;
        u32 d = sb + s * STAGEB + pdst;
        cp16(d,            pAh);      cp16(d + 16,            pAh + 8);
        if (npass == 2) {
            cp16(d + REGB,     pAl);  cp16(d + REGB + 16,     pAl + 8);
        }
        cp16(d + 2 * REGB, Bm + ob);  cp16(d + 2 * REGB + 16, Bm + ob + 8);
        cp_commit();
    };

    // consumer mapping: 8 warps -> 4 (m) x 2 (n); warp tile 32x64
    const int wr = wid & 3, wc = wid >> 2;
    const u32 a_off = (u32)((wr * 32 + (lane & 15)) * ROWB + (lane >> 4) * 16);
    const u32 b_off = (u32)(2 * REGB +
                            (wc * 64 + (lane & 7) + ((lane >> 4) & 1) * 8) * ROWB +
                            ((lane >> 3) & 1) * 16);

    float acc[2][8][4];
    #pragma unroll
    for (int i = 0; i < 2; i++)
        #pragma unroll
        for (int j = 0; j < 8; j++)
            #pragma unroll
            for (int q = 0; q < 4; q++) acc[i][j][q] = 0.f;

    issue(0, 0);
    if (ntiles > 1) issue(1, 1);

    for (int t = 0; t < ntiles; t++) {
        const int s = t & 1;
        if (t + 1 < ntiles) cp_wait1(); else cp_wait0();
        __syncthreads();   // stage s fully visible to all warps

        const u32 base = sb + s * STAGEB;
        #pragma unroll
        for (int kk = 0; kk < 32; kk += 16) {
            u32 ah[2][4], bx[4][4];
            #pragma unroll
            for (int mi = 0; mi < 2; mi++)
                ldsm4(ah[mi], base + a_off + mi * (16 * ROWB) + kk * 2);
            #pragma unroll
            for (int nj = 0; nj < 4; nj++)
                ldsm4(bx[nj], base + b_off + nj * (16 * ROWB) + kk * 2);
            // pass 1: Ah*B  (16 independent)
            #pragma unroll
            for (int mi = 0; mi < 2; mi++)
                #pragma unroll
                for (int nt = 0; nt < 8; nt++)
                    mma16816(acc[mi][nt], ah[mi], &bx[nt >> 1][(nt & 1) * 2]);
            // pass 2 (optional): Al*B
            if (npass == 2) {
                u32 al[2][4];
                #pragma unroll
                for (int mi = 0; mi < 2; mi++)
                    ldsm4(al[mi], base + REGB + a_off + mi * (16 * ROWB) + kk * 2);
                #pragma unroll
                for (int mi = 0; mi < 2; mi++)
                    #pragma unroll
                    for (int nt = 0; nt < 8; nt++)
                        mma16816(acc[mi][nt], al[mi], &bx[nt >> 1][(nt & 1) * 2]);
            }
        }
        __syncthreads();   // all warps done reading stage s
        if (t + 2 < ntiles) issue(t + 2, s);
    }

    // epilogue
    float* Cp = C + (long)blockIdx.z * partStride;
    const int gr  = bm + wr * 32 + (lane >> 2);
    const int gcb = bn + wc * 64 + (lane & 3) * 2;
    #pragma unroll
    for (int mi = 0; mi < 2; mi++)
        #pragma unroll
        for (int nt = 0; nt < 8; nt++) {
            int r0 = gr + mi * 16;
            int c  = gcb + nt * 8;
            float b0 = 0.f, b1 = 0.f;
            if (bias) { b0 = bias[c]; b1 = bias[c + 1]; }
            float2 v0 = make_float2(acc[mi][nt][0] + b0, acc[mi][nt][1] + b1);
            float2 v1 = make_float2(acc[mi][nt][2] + b0, acc[mi][nt][3] + b1);
            *(float2*)(Cp + (long)r0 * ldC + c)       = v0;
            *(float2*)(Cp + (long)(r0 + 8) * ldC + c) = v1;
        }
}

// ---------------- split-K combine + bias + residual + relu ----------------
__global__ void __launch_bounds__(256)
combine_layer(const float* __restrict__ bias,
              const float* __restrict__ xin,
              float* __restrict__ xout,
              __half* __restrict__ xh,
              __half* __restrict__ xl)
{
    const int i = blockIdx.x * 256 + threadIdx.x;      // over BSZ*DIM/4
    const float4* p = (const float4*)g_part;
    const int Q = BSZ * DIM / 4;
    float4 acc = p[i];
    #pragma unroll
    for (int q = 1; q < NSPLIT; q++) {
        float4 v = p[i + q * Q];
        acc.x += v.x; acc.y += v.y; acc.z += v.z; acc.w += v.w;
    }
    float4 xi = ((const float4*)xin)[i];
    float4 bb = ((const float4*)bias)[i & 31];
    float4 o;
    o.x = fmaxf(acc.x + xi.x + bb.x, 0.f);
    o.y = fmaxf(acc.y + xi.y + bb.y, 0.f);
    o.z = fmaxf(acc.z + xi.z + bb.z, 0.f);
    o.w = fmaxf(acc.w + xi.w + bb.w, 0.f);
    ((float4*)xout)[i] = o;

    __half hx, lx, hy, ly, hz, lz, hw, lw;
    split_f16(o.x, hx, lx); split_f16(o.y, hy, ly);
    split_f16(o.z, hz, lz); split_f16(o.w, hw, lw);
    __half2* ph = (__half2*)xh;
    __half2* pl = (__half2*)xl;
    ph[2 * i]     = __halves2half2(hx, hy);
    ph[2 * i + 1] = __halves2half2(hz, hw);
    pl[2 * i]     = __halves2half2(lx, ly);
    pl[2 * i + 1] = __halves2half2(lz, lw);
}

// ---------------- attention (L=2, one warp per head) ----------------
__global__ void __launch_bounds__(128)
attn_kernel()
{
    const int b = blockIdx.x;
    const int h = threadIdx.x >> 5;
    const int d = threadIdx.x & 31;

    const float* p0 = g_qkv + (long)b * NQKV + h * 32 + d;
    const float* p1 = p0 + (long)BSZ * NQKV;
    float q0 = p0[0], k0 = p0[128], v0 = p0[256];
    float q1 = p1[0], k1 = p1[128], v1 = p1[256];

    float s00 = q0 * k0, s01 = q0 * k1, s10 = q1 * k0, s11 = q1 * k1;
    #pragma unroll
    for (int o = 16; o; o >>= 1) {
        s00 += __shfl_xor_sync(0xffffffffu, s00, o);
        s01 += __shfl_xor_sync(0xffffffffu, s01, o);
        s10 += __shfl_xor_sync(0xffffffffu, s10, o);
        s11 += __shfl_xor_sync(0xffffffffu, s11, o);
    }
    const float inv = 0.17677669529663687f;  // 1/sqrt(32)
    s00 *= inv; s01 *= inv; s10 *= inv; s11 *= inv;

    float m0 = fmaxf(s00, s01), m1 = fmaxf(s10, s11);
    float e00 = expf(s00 - m0), e01 = expf(s01 - m0);
    float e10 = expf(s10 - m1), e11 = expf(s11 - m1);
    float o0 = (e00 * v0 + e01 * v1) / (e00 + e01);
    float o1 = (e10 * v0 + e11 * v1) / (e10 + e11);

    float v = 0.5f * (o0 + o1);
    __half hh, ll; split_f16(v, hh, ll);
    g_oh[(long)b * DIM + h * 32 + d] = hh;
    g_ol[(long)b * DIM + h * 32 + d] = ll;
}

// ---------------- host launcher ----------------
extern "C" void kernel_launch(void* const* d_in, const int* in_sizes, int n_in,
                              void* d_out, int out_size)
{
    const int*   drug = (const int*)  d_in[0];
    const int*   adjE = (const int*)  d_in[1];
    const int*   adjR = (const int*)  d_in[2];
    const float* ew   = (const float*)d_in[3];
    const float* E    = (const float*)d_in[4];
    const float* Wrel = (const float*)d_in[5];
    const float* resW = (const float*)d_in[6];
    const float* resb = (const float*)d_in[7];
    const float* inW  = (const float*)d_in[8];
    const float* inB  = (const float*)d_in[9];
    const float* outW = (const float*)d_in[10];
    const float* outB = (const float*)d_in[11];

    __half *aggh, *xh, *xl, *oh, *ol, *Wt, *inw, *outw;
    float *xf, *qkv, *part;
    cudaGetSymbolAddress((void**)&aggh, g_aggh);
    cudaGetSymbolAddress((void**)&xf,   g_x);
    cudaGetSymbolAddress((void**)&xh,   g_xh);
    cudaGetSymbolAddress((void**)&xl,   g_xl);
    cudaGetSymbolAddress((void**)&qkv,  g_qkv);
    cudaGetSymbolAddress((void**)&oh,   g_oh);
    cudaGetSymbolAddress((void**)&ol,   g_ol);
    cudaGetSymbolAddress((void**)&Wt,   g_Wt);
    cudaGetSymbolAddress((void**)&inw,  g_in);
    cudaGetSymbolAddress((void**)&outw, g_out);
    cudaGetSymbolAddress((void**)&part, g_part);

    cudaFuncSetAttribute(gemm_f16, cudaFuncAttributeMaxDynamicSharedMemorySize, GT_SMEM);

    transpose_wrel<<<dim3(4, 4, 32), dim3(32, 8)>>>(Wrel);
    prep_rest<<<(2 * DIM * DIM + NQKV * DIM + DIM * DIM + 255) / 256, 256>>>(resW, inW, outW);
    agg_kernel<<<BSZ, 128>>>(drug, adjE, adjR, ew, E);

    // layer 0 (single-pass fp16): part = split-K((agg|x0) @ Wcat0^T)
    gemm_f16<<<dim3(BSZ / 128, 1, NSPLIT), 256, GT_SMEM>>>(
        aggh, nullptr, KAGG, xh, nullptr, DIM, Wt, KCAT,
        part, DIM, (long)BSZ * DIM, LAYER_TILES, nullptr, 1);
    combine_layer<<<BSZ * DIM / 4 / 256, 256>>>(
        resb, xf, xf + BSZ * DIM, xh + BSZ * DIM, xl + BSZ * DIM);

    // layer 1 (single-pass fp16)
    gemm_f16<<<dim3(BSZ / 128, 1, NSPLIT), 256, GT_SMEM>>>(
        aggh, nullptr, KAGG, xh + BSZ * DIM, nullptr, DIM,
        Wt + DIM * KCAT, KCAT,
        part, DIM, (long)BSZ * DIM, LAYER_TILES, nullptr, 1);
    combine_layer<<<BSZ * DIM / 4 / 256, 256>>>(
        resb + DIM, xf + BSZ * DIM, xf + 2 * BSZ * DIM,
        xh + 2 * BSZ * DIM, xl + 2 * BSZ * DIM);

    // qkv for both layer outputs (2-pass): M=8192, N=384, K=128
    gemm_f16<<<dim3(2 * BSZ / 128, NQKV / 128, 1), 256, GT_SMEM>>>(
        xh + BSZ * DIM, xl + BSZ * DIM, DIM, nullptr, nullptr, 0,
        inw, DIM, qkv, NQKV, 0, 4, inB, 2);

    attn_kernel<<<BSZ, 128>>>();

    // out projection (2-pass): M=4096, N=128, K=128 -> d_out
    gemm_f16<<<dim3(BSZ / 128, 1, 1), 256, GT_SMEM>>>(
        oh, ol, DIM, nullptr, nullptr, 0,
        outw, DIM, (float*)d_out, DIM, 0, 4, outB, 2);
}

// round 12
// speedup vs baseline: 1.6248x; 1.0583x over previous
#include <cuda_runtime.h>
#include <cuda_fp16.h>
#include <math.h>
#include <stdint.h>

typedef unsigned long long u64;
typedef unsigned int u32;

// ---------------- problem constants ----------------
#define BSZ   4096
#define DIM   128
#define KNBR  64
#define NREL  16
#define KAGG  2048          // NREL * DIM
#define KCAT  2176          // KAGG + DIM
#define NQKV  384
#define NSPLIT 8            // split-K for layer GEMMs (68 tiles -> 8..9 each)
#define LAYER_TILES 68      // KCAT / 32

// ---------------- device scratch ----------------
__device__ __half g_aggh[BSZ * KAGG];
__device__ float  g_x   [3][BSZ * DIM];        // fp32 x0,x1 (residuals)
__device__ __half g_xh  [3 * BSZ * DIM];       // x0,x1,x2 hi
__device__ float  g_qkv [2 * BSZ * NQKV];
__device__ __half g_oh  [BSZ * DIM];
__device__ __half g_ol  [BSZ * DIM];
__device__ __half g_Wt  [2 * DIM * KCAT];      // B for layer gemm, [l][e][k], fp16
__device__ __half g_in  [NQKV * DIM];          // in_proj_w fp16
__device__ __half g_out [DIM * DIM];           // out_proj_w fp16
__device__ float  g_part[NSPLIT * BSZ * DIM];

// ================= PTX helpers =================
__device__ __forceinline__ u32 smem_u32(const void* p) {
    u32 a; asm("{ .reg .u64 t; cvta.to.shared.u64 t, %1; cvt.u32.u64 %0, t; }" : "=r"(a) : "l"(p));
    return a;
}
__device__ __forceinline__ void cp16(u32 s, const void* g) {
    asm volatile("cp.async.cg.shared.global [%0], [%1], 16;" :: "r"(s), "l"(g));
}
__device__ __forceinline__ void cp_commit() {
    asm volatile("cp.async.commit_group;" ::: "memory");
}
__device__ __forceinline__ void cp_wait0() {
    asm volatile("cp.async.wait_group 0;" ::: "memory");
}
__device__ __forceinline__ void cp_wait1() {
    asm volatile("cp.async.wait_group 1;" ::: "memory");
}
__device__ __forceinline__ void ldsm4(u32* r, u32 addr) {
    asm volatile("ldmatrix.sync.aligned.m8n8.x4.shared.b16 {%0,%1,%2,%3}, [%4];"
                 : "=r"(r[0]), "=r"(r[1]), "=r"(r[2]), "=r"(r[3]) : "r"(addr));
}
__device__ __forceinline__ void mma16816(float* c, const u32* a, const u32* b) {
    asm volatile(
        "mma.sync.aligned.m16n8k16.row.col.f32.f16.f16.f32 "
        "{%0,%1,%2,%3}, {%4,%5,%6,%7}, {%8,%9}, {%0,%1,%2,%3};"
        : "+f"(c[0]), "+f"(c[1]), "+f"(c[2]), "+f"(c[3])
        : "r"(a[0]), "r"(a[1]), "r"(a[2]), "r"(a[3]), "r"(b[0]), "r"(b[1]));
}
__device__ __forceinline__ void split_f16(float v, __half& h, __half& l) {
    h = __float2half_rn(v);
    l = __float2half_rn(v - __half2float(h));
}

// ================= merged prep kernel =================
// blocks [0,512): transpose W_rel[l,r,d,e] -> g_Wt[l][e][r*128+d]
// blocks [512,896): res_W copy + inW/outW fp16 conversion
__global__ void __launch_bounds__(256)
prep_all(const float* __restrict__ Wrel,
         const float* __restrict__ resW,
         const float* __restrict__ inW,
         const float* __restrict__ outW)
{
    const int blk = blockIdx.x;
    if (blk < 512) {
        __shared__ float tile[32][33];
        const int mat = blk >> 4;            // l*16 + r
        const int by  = (blk >> 2) & 3;
        const int bx  = blk & 3;
        const int l = mat >> 4, r = mat & 15;
        const int tx = threadIdx.x & 31, ty = threadIdx.x >> 5;
        const float* src = Wrel + (long)mat * 16384;
        int e_in = bx * 32 + tx;
        #pragma unroll
        for (int i = 0; i < 4; i++) {
            int d = by * 32 + ty + i * 8;
            tile[ty + i * 8][tx] = src[d * 128 + e_in];
        }
        __syncthreads();
        const long base = (long)l * (DIM * KCAT);
        #pragma unroll
        for (int i = 0; i < 4; i++) {
            int e = bx * 32 + ty + i * 8;
            int d = by * 32 + tx;
            g_Wt[base + (long)e * KCAT + r * 128 + d] = __float2half_rn(tile[tx][ty + i * 8]);
        }
    } else {
        int i = (blk - 512) * 256 + threadIdx.x;
        const int NR = 2 * DIM * DIM;         // 32768
        const int NI = NQKV * DIM;            // 49152
        const int NO = DIM * DIM;             // 16384
        if (i < NR) {
            int l = i >> 14, e = (i >> 7) & 127, d = i & 127;
            g_Wt[(long)l * (DIM * KCAT) + (long)e * KCAT + 2048 + d] = __float2half_rn(resW[i]);
        } else if (i < NR + NI) {
            int t = i - NR;
            g_in[t] = __float2half_rn(inW[t]);
        } else if (i < NR + NI + NO) {
            int t = i - NR - NI;
            g_out[t] = __float2half_rn(outW[t]);
        }
    }
}

// ---------------- agg: relation scatter + x0 gather (fp16 hi outputs) ------
__global__ void __launch_bounds__(128)
agg_kernel(const int* __restrict__ drug,
           const int* __restrict__ adjE,
           const int* __restrict__ adjR,
           const float* __restrict__ ew,
           const float* __restrict__ E)
{
    __shared__ float s[NREL * DIM];
    __shared__ int   se[KNBR];
    __shared__ int   sr[KNBR];
    __shared__ float sw[KNBR];

    const int b = blockIdx.x;
    const int d = threadIdx.x;

    #pragma unroll
    for (int r = 0; r < NREL; r++) s[r * DIM + d] = 0.f;

    if (d < KNBR) {
        se[d] = adjE[b * KNBR + d];
        sr[d] = adjR[b * KNBR + d];
        sw[d] = ew  [b * KNBR + d];
    }
    {
        float v = E[(long)drug[b] * DIM + d];
        g_x[0][b * DIM + d] = v;
        g_xh[b * DIM + d] = __float2half_rn(v);
    }
    __syncthreads();

    #pragma unroll 1
    for (int k = 0; k < KNBR; k += 4) {
        float e0 = E[(long)se[k + 0] * DIM + d];
        float e1 = E[(long)se[k + 1] * DIM + d];
        float e2 = E[(long)se[k + 2] * DIM + d];
        float e3 = E[(long)se[k + 3] * DIM + d];
        s[sr[k + 0] * DIM + d] += sw[k + 0] * e0;
        s[sr[k + 1] * DIM + d] += sw[k + 1] * e1;
        s[sr[k + 2] * DIM + d] += sw[k + 2] * e2;
        s[sr[k + 3] * DIM + d] += sw[k + 3] * e3;
    }
    const long ao = (long)b * KAGG;
    #pragma unroll
    for (int r = 0; r < NREL; r++)
        g_aggh[ao + r * DIM + d] = __float2half_rn(s[r * DIM + d]);
}

// ================= fp16 tensor-core GEMM, templated pass count =============
// 256 threads / 8 warps; CTA tile 128x128; warp tile 32x64; 2 CTAs/SM.
// C[m,n] = sum_k A[m,k]*B[n,k]; A = [A1 | A2] fp16 (lo limbs iff NPASS==2).
// 3-stage cp.async pipeline, ONE barrier per k-tile.
// SMEM per stage: NPASS==1 -> {Ah,B} = 20KB ; NPASS==2 -> {Ah,Al,B} = 30KB.
#define ROWB   80
#define REGB   10240            // 128 * 80

template<int NPASS>
__global__ void __launch_bounds__(256, 2)
gemm_f16(const __half* __restrict__ A1h, const __half* __restrict__ A1l, int K1,
         const __half* __restrict__ A2h, const __half* __restrict__ A2l, int K2,
         const __half* __restrict__ Bm, int KB,
         float* __restrict__ C, int ldC, long partStride,
         int tiles_total, const float* __restrict__ bias)
{
    constexpr u32 STAGE = (NPASS + 1) * REGB;
    constexpr u32 BOFF  = NPASS * REGB;

    extern __shared__ __align__(128) char smem[];
    const u32 sb  = smem_u32(smem);
    const int tid = threadIdx.x, lane = tid & 31, wid = tid >> 5;
    const int bm  = blockIdx.x * 128;
    const int bn  = blockIdx.y * 128;

    const int tb = (tiles_total * blockIdx.z) / gridDim.z;
    const int te = (tiles_total * (blockIdx.z + 1)) / gridDim.z;
    const int ntiles = te - tb;
    const int kbeg = tb * 32;

    // producer mapping: thread -> (row, 16-elem segment)
    const int prow = tid >> 1, pseg = tid & 1;
    const u32 pdst = (u32)(prow * ROWB + pseg * 32);

    auto issue = [&](int t, int s) {
        const int k0 = kbeg + t * 32;
        const __half *pAh, *pAl = nullptr;
        if (k0 < K1) {
            long o = (long)(bm + prow) * K1 + k0 + pseg * 16;
            pAh = A1h + o; if (NPASS == 2) pAl = A1l + o;
        } else {
            long o = (long)(bm + prow) * K2 + (k0 - K1) + pseg * 16;
            pAh = A2h + o; if (NPASS == 2) pAl = A2l + o;
        }
        long ob = (long)(bn + prow) * KB + k0 + pseg * 16;
        u32 d = sb + s * STAGE + pdst;
        cp16(d,        pAh);      cp16(d + 16,        pAh + 8);
        if (NPASS == 2) {
            cp16(d + REGB, pAl);  cp16(d + REGB + 16, pAl + 8);
        }
        cp16(d + BOFF, Bm + ob);  cp16(d + BOFF + 16, Bm + ob + 8);
        cp_commit();
    };

    // consumer mapping: 8 warps -> 4 (m) x 2 (n); warp tile 32x64
    const int wr = wid & 3, wc = wid >> 2;
    const u32 a_off = (u32)((wr * 32 + (lane & 15)) * ROWB + (lane >> 4) * 16);
    const u32 b_off = (u32)(BOFF +
                            (wc * 64 + (lane & 7) + ((lane >> 4) & 1) * 8) * ROWB +
                            ((lane >> 3) & 1) * 16);

    float acc[2][8][4];
    #pragma unroll
    for (int i = 0; i < 2; i++)
        #pragma unroll
        for (int j = 0; j < 8; j++)
            #pragma unroll
            for (int q = 0; q < 4; q++) acc[i][j][q] = 0.f;

    issue(0, 0);
    if (ntiles > 1) issue(1, 1);

    for (int t = 0; t < ntiles; t++) {
        const int s = t % 3;
        if (t + 1 < ntiles) cp_wait1(); else cp_wait0();
        __syncthreads();   // stage s visible; all warps done with stage (t+2)%3
        if (t + 2 < ntiles) issue(t + 2, (t + 2) % 3);

        const u32 base = sb + s * STAGE;
        #pragma unroll
        for (int kk = 0; kk < 32; kk += 16) {
            u32 ah[2][4], bx[4][4];
            #pragma unroll
            for (int mi = 0; mi < 2; mi++)
                ldsm4(ah[mi], base + a_off + mi * (16 * ROWB) + kk * 2);
            #pragma unroll
            for (int nj = 0; nj < 4; nj++)
                ldsm4(bx[nj], base + b_off + nj * (16 * ROWB) + kk * 2);
            #pragma unroll
            for (int mi = 0; mi < 2; mi++)
                #pragma unroll
                for (int nt = 0; nt < 8; nt++)
                    mma16816(acc[mi][nt], ah[mi], &bx[nt >> 1][(nt & 1) * 2]);
            if (NPASS == 2) {
                u32 al[2][4];
                #pragma unroll
                for (int mi = 0; mi < 2; mi++)
                    ldsm4(al[mi], base + REGB + a_off + mi * (16 * ROWB) + kk * 2);
                #pragma unroll
                for (int mi = 0; mi < 2; mi++)
                    #pragma unroll
                    for (int nt = 0; nt < 8; nt++)
                        mma16816(acc[mi][nt], al[mi], &bx[nt >> 1][(nt & 1) * 2]);
            }
        }
    }

    // epilogue
    float* Cp = C + (long)blockIdx.z * partStride;
    const int gr  = bm + wr * 32 + (lane >> 2);
    const int gcb = bn + wc * 64 + (lane & 3) * 2;
    #pragma unroll
    for (int mi = 0; mi < 2; mi++)
        #pragma unroll
        for (int nt = 0; nt < 8; nt++) {
            int r0 = gr + mi * 16;
            int c  = gcb + nt * 8;
            float b0 = 0.f, b1 = 0.f;
            if (bias) { b0 = bias[c]; b1 = bias[c + 1]; }
            float2 v0 = make_float2(acc[mi][nt][0] + b0, acc[mi][nt][1] + b1);
            float2 v1 = make_float2(acc[mi][nt][2] + b0, acc[mi][nt][3] + b1);
            *(float2*)(Cp + (long)r0 * ldC + c)       = v0;
            *(float2*)(Cp + (long)(r0 + 8) * ldC + c) = v1;
        }
}

// ---------------- split-K combine + bias + residual + relu ----------------
__global__ void __launch_bounds__(256)
combine_layer(const float* __restrict__ bias,
              const float* __restrict__ xin,
              float* __restrict__ xout,
              __half* __restrict__ xh)
{
    const int i = blockIdx.x * 256 + threadIdx.x;      // over BSZ*DIM/4
    const float4* p = (const float4*)g_part;
    const int Q = BSZ * DIM / 4;
    float4 acc = p[i];
    #pragma unroll
    for (int q = 1; q < NSPLIT; q++) {
        float4 v = p[i + q * Q];
        acc.x += v.x; acc.y += v.y; acc.z += v.z; acc.w += v.w;
    }
    float4 xi = ((const float4*)xin)[i];
    float4 bb = ((const float4*)bias)[i & 31];
    float4 o;
    o.x = fmaxf(acc.x + xi.x + bb.x, 0.f);
    o.y = fmaxf(acc.y + xi.y + bb.y, 0.f);
    o.z = fmaxf(acc.z + xi.z + bb.z, 0.f);
    o.w = fmaxf(acc.w + xi.w + bb.w, 0.f);
    ((float4*)xout)[i] = o;

    __half2* ph = (__half2*)xh;
    ph[2 * i]     = __halves2half2(__float2half_rn(o.x), __float2half_rn(o.y));
    ph[2 * i + 1] = __halves2half2(__float2half_rn(o.z), __float2half_rn(o.w));
}

// ---------------- attention (L=2, one warp per head) ----------------
__global__ void __launch_bounds__(128)
attn_kernel()
{
    const int b = blockIdx.x;
    const int h = threadIdx.x >> 5;
    const int d = threadIdx.x & 31;

    const float* p0 = g_qkv + (long)b * NQKV + h * 32 + d;
    const float* p1 = p0 + (long)BSZ * NQKV;
    float q0 = p0[0], k0 = p0[128], v0 = p0[256];
    float q1 = p1[0], k1 = p1[128], v1 = p1[256];

    float s00 = q0 * k0, s01 = q0 * k1, s10 = q1 * k0, s11 = q1 * k1;
    #pragma unroll
    for (int o = 16; o; o >>= 1) {
        s00 += __shfl_xor_sync(0xffffffffu, s00, o);
        s01 += __shfl_xor_sync(0xffffffffu, s01, o);
        s10 += __shfl_xor_sync(0xffffffffu, s10, o);
        s11 += __shfl_xor_sync(0xffffffffu, s11, o);
    }
    const float inv = 0.17677669529663687f;  // 1/sqrt(32)
    s00 *= inv; s01 *= inv; s10 *= inv; s11 *= inv;

    float m0 = fmaxf(s00, s01), m1 = fmaxf(s10, s11);
    float e00 = expf(s00 - m0), e01 = expf(s01 - m0);
    float e10 = expf(s10 - m1), e11 = expf(s11 - m1);
    float o0 = (e00 * v0 + e01 * v1) / (e00 + e01);
    float o1 = (e10 * v0 + e11 * v1) / (e10 + e11);

    float v = 0.5f * (o0 + o1);
    __half hh, ll; split_f16(v, hh, ll);
    g_oh[(long)b * DIM + h * 32 + d] = hh;
    g_ol[(long)b * DIM + h * 32 + d] = ll;
}

// ---------------- host launcher ----------------
extern "C" void kernel_launch(void* const* d_in, const int* in_sizes, int n_in,
                              void* d_out, int out_size)
{
    const int*   drug = (const int*)  d_in[0];
    const int*   adjE = (const int*)  d_in[1];
    const int*   adjR = (const int*)  d_in[2];
    const float* ew   = (const float*)d_in[3];
    const float* E    = (const float*)d_in[4];
    const float* Wrel = (const float*)d_in[5];
    const float* resW = (const float*)d_in[6];
    const float* resb = (const float*)d_in[7];
    const float* inW  = (const float*)d_in[8];
    const float* inB  = (const float*)d_in[9];
    const float* outW = (const float*)d_in[10];
    const float* outB = (const float*)d_in[11];

    __half *aggh, *xh, *oh, *ol, *Wt, *inw, *outw;
    float *xf, *qkv, *part;
    cudaGetSymbolAddress((void**)&aggh, g_aggh);
    cudaGetSymbolAddress((void**)&xf,   g_x);
    cudaGetSymbolAddress((void**)&xh,   g_xh);
    cudaGetSymbolAddress((void**)&qkv,  g_qkv);
    cudaGetSymbolAddress((void**)&oh,   g_oh);
    cudaGetSymbolAddress((void**)&ol,   g_ol);
    cudaGetSymbolAddress((void**)&Wt,   g_Wt);
    cudaGetSymbolAddress((void**)&inw,  g_in);
    cudaGetSymbolAddress((void**)&outw, g_out);
    cudaGetSymbolAddress((void**)&part, g_part);

    const int SM1 = 3 * 2 * REGB;   // 61440
    const int SM2 = 3 * 3 * REGB;   // 92160
    cudaFuncSetAttribute(gemm_f16<1>, cudaFuncAttributeMaxDynamicSharedMemorySize, SM1);
    cudaFuncSetAttribute(gemm_f16<2>, cudaFuncAttributeMaxDynamicSharedMemorySize, SM2);

    prep_all<<<896, 256>>>(Wrel, resW, inW, outW);
    agg_kernel<<<BSZ, 128>>>(drug, adjE, adjR, ew, E);

    // layer 0 (1-pass): part = split-K((agg|x0) @ Wcat0^T)
    gemm_f16<1><<<dim3(BSZ / 128, 1, NSPLIT), 256, SM1>>>(
        aggh, nullptr, KAGG, xh, nullptr, DIM, Wt, KCAT,
        part, DIM, (long)BSZ * DIM, LAYER_TILES, nullptr);
    combine_layer<<<BSZ * DIM / 4 / 256, 256>>>(
        resb, xf, xf + BSZ * DIM, xh + BSZ * DIM);

    // layer 1 (1-pass)
    gemm_f16<1><<<dim3(BSZ / 128, 1, NSPLIT), 256, SM1>>>(
        aggh, nullptr, KAGG, xh + BSZ * DIM, nullptr, DIM,
        Wt + DIM * KCAT, KCAT,
        part, DIM, (long)BSZ * DIM, LAYER_TILES, nullptr);
    combine_layer<<<BSZ * DIM / 4 / 256, 256>>>(
        resb + DIM, xf + BSZ * DIM, xf + 2 * BSZ * DIM,
        xh + 2 * BSZ * DIM);

    // qkv for both layer outputs (1-pass): M=8192, N=384, K=128
    gemm_f16<1><<<dim3(2 * BSZ / 128, NQKV / 128, 1), 256, SM1>>>(
        xh + BSZ * DIM, nullptr, DIM, nullptr, nullptr, 0,
        inw, DIM, qkv, NQKV, 0, 4, inB);

    attn_kernel<<<BSZ, 128>>>();

    // out projection (2-pass): M=4096, N=128, K=128 -> d_out
    gemm_f16<2><<<dim3(BSZ / 128, 1, 1), 256, SM2>>>(
        oh, ol, DIM, nullptr, nullptr, 0,
        outw, DIM, (float*)d_out, DIM, 0, 4, outB);
}